// round 15
// baseline (speedup 1.0000x reference)
#include <cuda_runtime.h>
#include <cuda_bf16.h>
#include <math.h>
#include <stdint.h>

typedef __nv_bfloat16 bf16;

// ---------------- problem constants ----------------
#define Tt 16
#define Cc 512
#define HEADS 16
#define DH 64
#define INNER 1024   // HEADS*DH
#define MLP 2048     // 4*C
#define DEPTH 2
#define MAXT 32
#define Ss 144       // H*W
#define Nn_TOK 2304  // T*S
#define SCALE 0.125f
#define SC2 (0.125f * 1.4426950408889634f)   // SCALE * log2(e)
#define EPS 1e-5f
#define QKN 2048     // fused Q|K projection width

// ---------------- scratch (device globals; no runtime alloc) -------------
__device__ __align__(256) float g_xt[Nn_TOK * Cc];
__device__ __align__(256) float g_yt[Nn_TOK * Cc];
__device__ __align__(256) bf16  g_xn_h[Nn_TOK * Cc];
__device__ __align__(256) bf16  g_xn_l[Nn_TOK * Cc];
__device__ __align__(256) bf16  g_yn_h[Nn_TOK * Cc];
__device__ __align__(256) bf16  g_yn_l[Nn_TOK * Cc];
__device__ __align__(256) float g_proj[Nn_TOK * Cc];
__device__ __align__(256) float g_qk[Nn_TOK * QKN];
__device__ __align__(256) float g_v[Nn_TOK * INNER];
__device__ __align__(256) bf16  g_ao_h[Nn_TOK * INNER];
__device__ __align__(256) bf16  g_ao_l[Nn_TOK * INNER];
__device__ __align__(256) bf16  g_h_h[Nn_TOK * MLP];
__device__ __align__(256) bf16  g_h_l[Nn_TOK * MLP];
// rope tables
__device__ __align__(256) float g_rcos[Nn_TOK * 32];
__device__ __align__(256) float g_rsin[Nn_TOK * 32];
// per-head attention operand layouts
__device__ __align__(256) bf16 g_qh[HEADS * Nn_TOK * DH];
__device__ __align__(256) bf16 g_kh[HEADS * Nn_TOK * DH];
__device__ __align__(256) bf16 g_vth[HEADS * DH * Nn_TOK];  // [h][d][n]
__device__ __align__(256) bf16 g_vtl[HEADS * DH * Nn_TOK];
// transposed + split weights [N,K] bf16
__device__ __align__(256) bf16 g_wqkt_h[QKN * Cc];
__device__ __align__(256) bf16 g_wqkt_l[QKN * Cc];
__device__ __align__(256) bf16 g_wvt_h[INNER * Cc];
__device__ __align__(256) bf16 g_wvt_l[INNER * Cc];
__device__ __align__(256) bf16 g_owt_h[Cc * INNER];
__device__ __align__(256) bf16 g_owt_l[Cc * INNER];
__device__ __align__(256) bf16 g_w1t_h[MLP * Cc];
__device__ __align__(256) bf16 g_w1t_l[MLP * Cc];
__device__ __align__(256) bf16 g_w2t_h[Cc * MLP];
__device__ __align__(256) bf16 g_w2t_l[Cc * MLP];

// ---------------- low-level helpers ----------------
__device__ __forceinline__ uint32_t smem_u32(const void* p) {
    uint32_t a;
    asm("{ .reg .u64 t; cvta.to.shared.u64 t, %1; cvt.u32.u64 %0, t; }" : "=r"(a) : "l"(p));
    return a;
}
__device__ __forceinline__ void cp16(uint32_t dst, const void* src) {
    asm volatile("cp.async.cg.shared.global [%0], [%1], 16;" :: "r"(dst), "l"(src));
}
__device__ __forceinline__ void cp_commit() { asm volatile("cp.async.commit_group;"); }
__device__ __forceinline__ void cp_wait1() { asm volatile("cp.async.wait_group 1;"); }

__device__ __forceinline__ void mma16816(float* c, const uint32_t* a, uint32_t b0, uint32_t b1) {
    asm volatile(
        "mma.sync.aligned.m16n8k16.row.col.f32.bf16.bf16.f32 "
        "{%0,%1,%2,%3}, {%4,%5,%6,%7}, {%8,%9}, {%0,%1,%2,%3};"
        : "+f"(c[0]), "+f"(c[1]), "+f"(c[2]), "+f"(c[3])
        : "r"(a[0]), "r"(a[1]), "r"(a[2]), "r"(a[3]), "r"(b0), "r"(b1));
}
__device__ __forceinline__ void ldsm4(uint32_t* r, uint32_t addr) {
    asm volatile("ldmatrix.sync.aligned.m8n8.x4.shared.b16 {%0,%1,%2,%3}, [%4];"
                 : "=r"(r[0]), "=r"(r[1]), "=r"(r[2]), "=r"(r[3]) : "r"(addr));
}
__device__ __forceinline__ uint32_t packbf(float x, float y) {
    __nv_bfloat162 t = __float22bfloat162_rn(make_float2(x, y));
    return *reinterpret_cast<uint32_t*>(&t);
}
__device__ __forceinline__ void split2(float v, bf16& h, bf16& l) {
    h = __float2bfloat16(v);
    l = __float2bfloat16(v - __bfloat162float(h));
}
// fast GELU: tanh(y) = 1 - 2/(1+exp(2y)) via __expf (error ~1e-7 rel in output)
__device__ __forceinline__ float gelu_fast(float x) {
    const float cg = 0.7978845608028654f;
    float y = cg * (x + 0.044715f * x * x * x);
    float t = 1.0f - 2.0f / (1.0f + __expf(2.0f * y));
    return 0.5f * x * (1.0f + t);
}

// ---------------- pack: x[T,C,S] -> xt[T*S,C] (tiled transpose) ----------
__global__ void pack_in_kernel(const float* __restrict__ x, const float* __restrict__ y,
                               float* __restrict__ xt, float* __restrict__ yt) {
    __shared__ float sm[16][68];
    int sb = blockIdx.x * 16, cb = blockIdx.y * 64, t = blockIdx.z;
    int tid = threadIdx.x;
    int sl = tid & 15, cl = tid >> 4;
    int cl2 = tid & 63, sl2 = tid >> 6;

    const float* srcs[2] = { x, y };
    float* dsts[2] = { xt, yt };
#pragma unroll
    for (int a = 0; a < 2; a++) {
#pragma unroll
        for (int i = 0; i < 4; i++)
            sm[sl][cl + 16 * i] = srcs[a][((size_t)t * Cc + cb + cl + 16 * i) * Ss + sb + sl];
        __syncthreads();
#pragma unroll
        for (int p = 0; p < 4; p++)
            dsts[a][((size_t)t * Ss + sb + sl2 + 4 * p) * Cc + cb + cl2] = sm[sl2 + 4 * p][cl2];
        __syncthreads();
    }
}
// xt[T*S,C] -> out[T,C,S]
__global__ void pack_out_kernel(const float* __restrict__ xt, float* __restrict__ out) {
    __shared__ float sm[16][68];
    int sb = blockIdx.x * 16, cb = blockIdx.y * 64, t = blockIdx.z;
    int tid = threadIdx.x;
    int cl = tid & 63, sl = tid >> 6;
    int sl2 = tid & 15, cl2 = tid >> 4;
#pragma unroll
    for (int p = 0; p < 4; p++)
        sm[sl + 4 * p][cl] = xt[((size_t)t * Ss + sb + sl + 4 * p) * Cc + cb + cl];
    __syncthreads();
#pragma unroll
    for (int i = 0; i < 4; i++)
        out[((size_t)t * Cc + cb + cl2 + 16 * i) * Ss + sb + sl2] = sm[sl2][cl2 + 16 * i];
}

// ---------------- fused x/y LayerNorm (+pos) -> bf16 hi/lo ----------
__global__ void ln2_kernel(const float* __restrict__ xin, const float* __restrict__ yin,
                           bf16* __restrict__ xh, bf16* __restrict__ xl,
                           bf16* __restrict__ yh, bf16* __restrict__ yl,
                           const float* __restrict__ gx, const float* __restrict__ bx,
                           const float* __restrict__ gy, const float* __restrict__ by,
                           const float* __restrict__ pos) {
    __shared__ float red[4];
    int row = blockIdx.x;
    int which = blockIdx.y;
    const float* in = which ? yin : xin;
    bf16* oh = which ? yh : xh;
    bf16* ol = which ? yl : xl;
    const float* gamma = which ? gy : gx;
    const float* beta  = which ? by : bx;
    int tid = threadIdx.x;
    const float* x = in + (size_t)row * Cc;

    float v[4];
    float s = 0.f;
#pragma unroll
    for (int l = 0; l < 4; l++) { v[l] = x[tid + l * 128]; s += v[l]; }
#pragma unroll
    for (int o = 16; o > 0; o >>= 1) s += __shfl_xor_sync(0xffffffffu, s, o);
    int warp = tid >> 5, lane = tid & 31;
    if (lane == 0) red[warp] = s;
    __syncthreads();
    float mean = (red[0] + red[1] + red[2] + red[3]) * (1.0f / Cc);
    __syncthreads();
    float sq = 0.f;
#pragma unroll
    for (int l = 0; l < 4; l++) { float d = v[l] - mean; sq += d * d; }
#pragma unroll
    for (int o = 16; o > 0; o >>= 1) sq += __shfl_xor_sync(0xffffffffu, sq, o);
    if (lane == 0) red[warp] = sq;
    __syncthreads();
    float var = (red[0] + red[1] + red[2] + red[3]) * (1.0f / Cc);
    float inv = rsqrtf(var + EPS);

    int t = row / Ss;
#pragma unroll
    for (int l = 0; l < 4; l++) {
        int c = tid + l * 128;
        float val = (v[l] - mean) * inv * gamma[c] + beta[c] + pos[t * Cc + c];
        bf16 h, lo;
        split2(val, h, lo);
        oh[(size_t)row * Cc + c] = h;
        ol[(size_t)row * Cc + c] = lo;
    }
}

// ---------------- fused gate+residual+FFN-LN ----------------
__global__ void gate_ln_kernel(const float* __restrict__ proj,
                               const float* __restrict__ gw, const float* __restrict__ gb,
                               const float* __restrict__ gamma, const float* __restrict__ beta,
                               float* __restrict__ xt, bf16* __restrict__ oh, bf16* __restrict__ ol) {
    __shared__ float red[4];
    int row = blockIdx.x;
    int tid = threadIdx.x;
    int warp = tid >> 5, lane = tid & 31;
    const float* p = proj + (size_t)row * Cc;
    float* xr = xt + (size_t)row * Cc;

    float pv[4], xv[4];
    float s = 0.f;
#pragma unroll
    for (int l = 0; l < 4; l++) {
        int c = tid + l * 128;
        pv[l] = p[c];
        xv[l] = xr[c];
        s += pv[l] * gw[c];
    }
#pragma unroll
    for (int o = 16; o > 0; o >>= 1) s += __shfl_xor_sync(0xffffffffu, s, o);
    if (lane == 0) red[warp] = s;
    __syncthreads();
    float dot = red[0] + red[1] + red[2] + red[3];
    float g = 1.0f / (1.0f + __expf(-(dot + gb[0])));
    __syncthreads();

    float sum = 0.f;
#pragma unroll
    for (int l = 0; l < 4; l++) { xv[l] += pv[l] * g; sum += xv[l]; }
#pragma unroll
    for (int o = 16; o > 0; o >>= 1) sum += __shfl_xor_sync(0xffffffffu, sum, o);
    if (lane == 0) red[warp] = sum;
    __syncthreads();
    float mean = (red[0] + red[1] + red[2] + red[3]) * (1.0f / Cc);
    __syncthreads();
    float sq = 0.f;
#pragma unroll
    for (int l = 0; l < 4; l++) { float d = xv[l] - mean; sq += d * d; }
#pragma unroll
    for (int o = 16; o > 0; o >>= 1) sq += __shfl_xor_sync(0xffffffffu, sq, o);
    if (lane == 0) red[warp] = sq;
    __syncthreads();
    float var = (red[0] + red[1] + red[2] + red[3]) * (1.0f / Cc);
    float inv = rsqrtf(var + EPS);

#pragma unroll
    for (int l = 0; l < 4; l++) {
        int c = tid + l * 128;
        xr[c] = xv[l];
        float val = (xv[l] - mean) * inv * gamma[c] + beta[c];
        bf16 h, lo;
        split2(val, h, lo);
        oh[(size_t)row * Cc + c] = h;
        ol[(size_t)row * Cc + c] = lo;
    }
}

// ---------------- transpose + split body ----------------
__device__ __forceinline__ void tsplit_body(const float* __restrict__ W, bf16* __restrict__ hi,
                                            bf16* __restrict__ lo, int K, int N,
                                            int nb, int kb, int tid) {
    __shared__ float t[64][65];
    int kr = tid >> 4;
    int c4 = tid & 15;
#pragma unroll
    for (int i = 0; i < 4; i++) {
        int k = kr + 16 * i;
        float4 v = *reinterpret_cast<const float4*>(&W[(size_t)(kb + k) * N + nb + c4 * 4]);
        t[c4 * 4 + 0][k] = v.x; t[c4 * 4 + 1][k] = v.y;
        t[c4 * 4 + 2][k] = v.z; t[c4 * 4 + 3][k] = v.w;
    }
    __syncthreads();
    int n = tid >> 2;
    int k0 = (tid & 3) * 16;
    uint32_t hbuf[8], lbuf[8];
#pragma unroll
    for (int j = 0; j < 8; j++) {
        float v0 = t[n][k0 + 2 * j], v1 = t[n][k0 + 2 * j + 1];
        bf16 h0, l0, h1, l1;
        split2(v0, h0, l0); split2(v1, h1, l1);
        __nv_bfloat162 hh; hh.x = h0; hh.y = h1;
        __nv_bfloat162 ll; ll.x = l0; ll.y = l1;
        hbuf[j] = *reinterpret_cast<uint32_t*>(&hh);
        lbuf[j] = *reinterpret_cast<uint32_t*>(&ll);
    }
    size_t o = (size_t)(nb + n) * K + kb + k0;
    *reinterpret_cast<uint4*>(&hi[o])     = *reinterpret_cast<uint4*>(&hbuf[0]);
    *reinterpret_cast<uint4*>(&hi[o + 8]) = *reinterpret_cast<uint4*>(&hbuf[4]);
    *reinterpret_cast<uint4*>(&lo[o])     = *reinterpret_cast<uint4*>(&lbuf[0]);
    *reinterpret_cast<uint4*>(&lo[o + 8]) = *reinterpret_cast<uint4*>(&lbuf[4]);
}

// fused QKV weight split: z=0 wq, z=1 wk (into wqkt at offset), z=2 wv
__global__ void tsplit_qkv(const float* __restrict__ wq, const float* __restrict__ wk,
                           const float* __restrict__ wv,
                           bf16* __restrict__ qkt_h, bf16* __restrict__ qkt_l,
                           bf16* __restrict__ vt_h, bf16* __restrict__ vt_l) {
    int z = blockIdx.z;
    const float* W = (z == 0) ? wq : (z == 1) ? wk : wv;
    bf16* hi = (z == 0) ? qkt_h : (z == 1) ? qkt_h + (size_t)INNER * Cc : vt_h;
    bf16* lo = (z == 0) ? qkt_l : (z == 1) ? qkt_l + (size_t)INNER * Cc : vt_l;
    tsplit_body(W, hi, lo, Cc, INNER, blockIdx.x * 64, blockIdx.y * 64, threadIdx.x);
}

// fused ow/w1/w2 weight split: 1-D grid of 128+256+256 = 640 blocks
__global__ void tsplit3(const float* __restrict__ ow, const float* __restrict__ w1,
                        const float* __restrict__ w2,
                        bf16* __restrict__ owh, bf16* __restrict__ owl,
                        bf16* __restrict__ w1h, bf16* __restrict__ w1l,
                        bf16* __restrict__ w2h, bf16* __restrict__ w2l) {
    int b = blockIdx.x;
    const float* W; bf16 *hi, *lo; int K, N, lb;
    if (b < 128)      { W = ow; hi = owh; lo = owl; K = INNER; N = Cc;  lb = b; }
    else if (b < 384) { W = w1; hi = w1h; lo = w1l; K = Cc;    N = MLP; lb = b - 128; }
    else              { W = w2; hi = w2h; lo = w2l; K = MLP;   N = Cc;  lb = b - 384; }
    int nT = N / 64;
    tsplit_body(W, hi, lo, K, N, (lb % nT) * 64, (lb / nT) * 64, threadIdx.x);
}

// ---------------- mma.sync bf16 GEMM (hi/lo split, ldmatrix, 3-stage) -----
#define GROW80 80
#define GBUF_A (128 * 80)

template <int BN>
__global__ void gemm_mma(const bf16* __restrict__ Ah, const bf16* __restrict__ Al,
                         const bf16* __restrict__ Bh, const bf16* __restrict__ Bl,
                         const float* __restrict__ bias, const float* __restrict__ resid,
                         float* __restrict__ outF, bf16* __restrict__ outH, bf16* __restrict__ outL,
                         int Nc, int K, int act) {
    constexpr int WM = (BN == 128) ? 2 : 4;
    constexpr int MT = (BN == 128) ? 4 : 2;
    constexpr int GBUF_B = BN * 80;
    constexpr int GSTAGE = 2 * GBUF_A + 2 * GBUF_B;

    extern __shared__ char smemc[];
    uint32_t sb = smem_u32(smemc);
    int tid = threadIdx.x, wid = tid >> 5, lane = tid & 31;
    int gr = lane >> 2, cq = lane & 3;
    int mat = lane >> 3, rr = lane & 7;
    int wm = wid % WM, wn = wid / WM;
    int rowBase = blockIdx.y * 128, colBase = blockIdx.x * BN;
    int nc = K >> 5;

    const bf16* srcs[4] = { Ah + (size_t)rowBase * K, Al + (size_t)rowBase * K,
                            Bh + (size_t)colBase * K, Bl + (size_t)colBase * K };

    auto load_stage = [&](int kc, int s) {
        uint32_t base = sb + s * GSTAGE;
#pragma unroll
        for (int arr = 0; arr < 4; arr++) {
            int rows = (arr < 2) ? 128 : BN;
            const bf16* src = srcs[arr] + kc * 32;
            uint32_t dstb = base + ((arr < 2) ? arr * GBUF_A : 2 * GBUF_A + (arr - 2) * GBUF_B);
            for (int l = 0; l < rows * 4 / 256; l++) {
                int lin = tid + l * 256;
                int r = lin >> 2, ch = lin & 3;
                cp16(dstb + r * 80 + ch * 16, src + (size_t)r * K + ch * 8);
            }
        }
    };

    load_stage(0, 0); cp_commit();
    load_stage(1, 1); cp_commit();

    float acc[MT][4][4];
#pragma unroll
    for (int a = 0; a < MT; a++)
#pragma unroll
        for (int b = 0; b < 4; b++)
#pragma unroll
            for (int c = 0; c < 4; c++) acc[a][b][c] = 0.f;

    for (int kc = 0; kc < nc; kc++) {
        int s = kc % 3;
        cp_wait1();
        __syncthreads();
        uint32_t A0 = sb + s * GSTAGE, A1 = A0 + GBUF_A;
        uint32_t B0 = A0 + 2 * GBUF_A, B1 = B0 + GBUF_B;
#pragma unroll
        for (int ks = 0; ks < 2; ks++) {
            uint32_t af[2][MT][4];
#pragma unroll
            for (int mt = 0; mt < MT; mt++) {
                uint32_t ra = (uint32_t)(16 * MT * wm + 16 * mt + (mat & 1) * 8 + rr) * GROW80
                            + ks * 32 + (mat >> 1) * 16;
                ldsm4(af[0][mt], A0 + ra);
                ldsm4(af[1][mt], A1 + ra);
            }
#pragma unroll
            for (int ntp = 0; ntp < 2; ntp++) {
                uint32_t rb = (uint32_t)(32 * wn + 16 * ntp + (mat >> 1) * 8 + rr) * GROW80
                            + ks * 32 + (mat & 1) * 16;
                uint32_t bh[4], bl[4];
                ldsm4(bh, B0 + rb);
                ldsm4(bl, B1 + rb);
#pragma unroll
                for (int mt = 0; mt < MT; mt++) {
                    mma16816(acc[mt][2 * ntp], af[0][mt], bh[0], bh[1]);
                    mma16816(acc[mt][2 * ntp], af[0][mt], bl[0], bl[1]);
                    mma16816(acc[mt][2 * ntp], af[1][mt], bh[0], bh[1]);
                    mma16816(acc[mt][2 * ntp + 1], af[0][mt], bh[2], bh[3]);
                    mma16816(acc[mt][2 * ntp + 1], af[0][mt], bl[2], bl[3]);
                    mma16816(acc[mt][2 * ntp + 1], af[1][mt], bh[2], bh[3]);
                }
            }
        }
        if (kc + 2 < nc) load_stage(kc + 2, (kc + 2) % 3);
        cp_commit();
    }

#pragma unroll
    for (int mt = 0; mt < MT; mt++) {
#pragma unroll
        for (int nt = 0; nt < 4; nt++) {
            int col = colBase + 32 * wn + 8 * nt + 2 * cq;
#pragma unroll
            for (int half = 0; half < 2; half++) {
                int row = rowBase + 16 * MT * wm + 16 * mt + gr + 8 * half;
                float v0 = acc[mt][nt][2 * half + 0];
                float v1 = acc[mt][nt][2 * half + 1];
                if (bias) { v0 += bias[col]; v1 += bias[col + 1]; }
                if (resid) {
                    float2 rv = *reinterpret_cast<const float2*>(&resid[(size_t)row * Nc + col]);
                    v0 += rv.x; v1 += rv.y;
                }
                if (act == 1) {
                    v0 = gelu_fast(v0);
                    v1 = gelu_fast(v1);
                }
                if (outF)
                    *reinterpret_cast<float2*>(&outF[(size_t)row * Nc + col]) = make_float2(v0, v1);
                if (outH) {
                    bf16 h0, l0, h1, l1;
                    split2(v0, h0, l0);
                    split2(v1, h1, l1);
                    __nv_bfloat162 hh; hh.x = h0; hh.y = h1;
                    __nv_bfloat162 ll; ll.x = l0; ll.y = l1;
                    *reinterpret_cast<uint32_t*>(&outH[(size_t)row * Nc + col]) =
                        *reinterpret_cast<uint32_t*>(&hh);
                    *reinterpret_cast<uint32_t*>(&outL[(size_t)row * Nc + col]) =
                        *reinterpret_cast<uint32_t*>(&ll);
                }
            }
        }
    }
}

#define GEMM_SMEM128 (3 * (2 * GBUF_A + 2 * 128 * 80))  // 122880
#define GEMM_SMEM64  (3 * (2 * GBUF_A + 2 * 64 * 80))   // 92160

// ---------------- rope table ----------------
__global__ void rope_tab(float* __restrict__ rc, float* __restrict__ rs) {
    int idx = blockIdx.x * blockDim.x + threadIdx.x;
    if (idx >= Nn_TOK * 32) return;
    int j = idx & 31, n = idx >> 5;
    const float LOG1E4_OVER32 = 9.210340371976184f / 32.0f;
    float f = __expf(-(float)j * LOG1E4_OVER32);
    float ang = (float)n * f;
    rc[idx] = cosf(ang);
    rs[idx] = sinf(ang);
}

// ---------------- RoPE + pack into per-head layout (hi-only q,k) -------
__global__ void rope_split(const float* __restrict__ qk,
                           const float* __restrict__ rc, const float* __restrict__ rs,
                           bf16* __restrict__ qh_, bf16* __restrict__ kh_) {
    int idx = blockIdx.x * blockDim.x + threadIdx.x;
    if (idx >= Nn_TOK * HEADS * 4) return;
    int j8 = idx & 3;
    int nh = idx >> 2;
    int h = nh & 15;
    int n = nh >> 4;
    int j = j8 * 8;

    float c[8], s[8], a[8], b[8], ka[8], kb[8];
    *reinterpret_cast<float4*>(c)     = *reinterpret_cast<const float4*>(&rc[n * 32 + j]);
    *reinterpret_cast<float4*>(c + 4) = *reinterpret_cast<const float4*>(&rc[n * 32 + j + 4]);
    *reinterpret_cast<float4*>(s)     = *reinterpret_cast<const float4*>(&rs[n * 32 + j]);
    *reinterpret_cast<float4*>(s + 4) = *reinterpret_cast<const float4*>(&rs[n * 32 + j + 4]);

    size_t srcq = (size_t)n * QKN + h * DH;
    size_t srck = srcq + INNER;
    *reinterpret_cast<float4*>(a)      = *reinterpret_cast<const float4*>(&qk[srcq + j]);
    *reinterpret_cast<float4*>(a + 4)  = *reinterpret_cast<const float4*>(&qk[srcq + j + 4]);
    *reinterpret_cast<float4*>(b)      = *reinterpret_cast<const float4*>(&qk[srcq + j + 32]);
    *reinterpret_cast<float4*>(b + 4)  = *reinterpret_cast<const float4*>(&qk[srcq + j + 36]);
    *reinterpret_cast<float4*>(ka)     = *reinterpret_cast<const float4*>(&qk[srck + j]);
    *reinterpret_cast<float4*>(ka + 4) = *reinterpret_cast<const float4*>(&qk[srck + j + 4]);
    *reinterpret_cast<float4*>(kb)     = *reinterpret_cast<const float4*>(&qk[srck + j + 32]);
    *reinterpret_cast<float4*>(kb + 4) = *reinterpret_cast<const float4*>(&qk[srck + j + 36]);

    size_t dst = ((size_t)h * Nn_TOK + n) * DH;
    uint32_t qh1[4], qh2[4], kh1[4], kh2[4];
#pragma unroll
    for (int i = 0; i < 4; i++) {
        float r1a = a[2 * i] * c[2 * i] - b[2 * i] * s[2 * i];
        float r1b = a[2 * i + 1] * c[2 * i + 1] - b[2 * i + 1] * s[2 * i + 1];
        float r2a = b[2 * i] * c[2 * i] + a[2 * i] * s[2 * i];
        float r2b = b[2 * i + 1] * c[2 * i + 1] + a[2 * i + 1] * s[2 * i + 1];
        qh1[i] = packbf(r1a, r1b);
        qh2[i] = packbf(r2a, r2b);

        float k1a = ka[2 * i] * c[2 * i] - kb[2 * i] * s[2 * i];
        float k1b = ka[2 * i + 1] * c[2 * i + 1] - kb[2 * i + 1] * s[2 * i + 1];
        float k2a = kb[2 * i] * c[2 * i] + ka[2 * i] * s[2 * i];
        float k2b = kb[2 * i + 1] * c[2 * i + 1] + ka[2 * i + 1] * s[2 * i + 1];
        kh1[i] = packbf(k1a, k1b);
        kh2[i] = packbf(k2a, k2b);
    }
    *reinterpret_cast<uint4*>(&qh_[dst + j])      = *reinterpret_cast<uint4*>(qh1);
    *reinterpret_cast<uint4*>(&qh_[dst + j + 32]) = *reinterpret_cast<uint4*>(qh2);
    *reinterpret_cast<uint4*>(&kh_[dst + j])      = *reinterpret_cast<uint4*>(kh1);
    *reinterpret_cast<uint4*>(&kh_[dst + j + 32]) = *reinterpret_cast<uint4*>(kh2);
}

// ---------------- V transpose + split (64x64 tiles, vectorized) ----------
// grid (Nn_TOK/64, HEADS), block 256
__global__ void vt_split(const float* __restrict__ v, bf16* __restrict__ vh_, bf16* __restrict__ vl_) {
    __shared__ float tsm[64][65];
    int n0 = blockIdx.x * 64;
    int h = blockIdx.y;
    int tid = threadIdx.x;
    int r = tid >> 4, c4 = tid & 15;
#pragma unroll
    for (int i = 0; i < 4; i++) {
        int row = r + 16 * i;
        float4 val = *reinterpret_cast<const float4*>(&v[(size_t)(n0 + row) * INNER + h * DH + c4 * 4]);
        tsm[c4 * 4 + 0][row] = val.x; tsm[c4 * 4 + 1][row] = val.y;
        tsm[c4 * 4 + 2][row] = val.z; tsm[c4 * 4 + 3][row] = val.w;
    }
    __syncthreads();
    int d = tid >> 2;
    int nn0 = (tid & 3) * 16;
    uint32_t hbuf[8], lbuf[8];
#pragma unroll
    for (int j = 0; j < 8; j++) {
        float v0 = tsm[d][nn0 + 2 * j], v1 = tsm[d][nn0 + 2 * j + 1];
        bf16 h0, l0, h1, l1;
        split2(v0, h0, l0); split2(v1, h1, l1);
        __nv_bfloat162 hh; hh.x = h0; hh.y = h1;
        __nv_bfloat162 ll; ll.x = l0; ll.y = l1;
        hbuf[j] = *reinterpret_cast<uint32_t*>(&hh);
        lbuf[j] = *reinterpret_cast<uint32_t*>(&ll);
    }
    size_t o = ((size_t)h * DH + d) * Nn_TOK + n0 + nn0;
    *reinterpret_cast<uint4*>(&vh_[o])     = *reinterpret_cast<uint4*>(&hbuf[0]);
    *reinterpret_cast<uint4*>(&vh_[o + 8]) = *reinterpret_cast<uint4*>(&hbuf[4]);
    *reinterpret_cast<uint4*>(&vl_[o])     = *reinterpret_cast<uint4*>(&lbuf[0]);
    *reinterpret_cast<uint4*>(&vl_[o + 8]) = *reinterpret_cast<uint4*>(&lbuf[4]);
}

// ---------------- flash attention via mma.sync + ldmatrix (3-stage) -------
// 128 q-rows / CTA, 256 threads. Q hi-only, K hi-only; V hi+lo. log2-domain softmax.
#define AST144 144
#define ATILE (64 * 144)
#define ASTAGE (3 * ATILE)       // Kh, Vh, Vl
#define ATTN_SMEM (3 * ASTAGE)   // 82944 B

__global__ __launch_bounds__(256)
void attn_mma(const bf16* __restrict__ qh, const bf16* __restrict__ kh,
              const bf16* __restrict__ vth, const bf16* __restrict__ vtl,
              const int* __restrict__ mask,
              bf16* __restrict__ oh, bf16* __restrict__ ol) {
    extern __shared__ char smemc[];
    uint32_t sb = smem_u32(smemc);
    int h = blockIdx.y;
    int qbase = blockIdx.x * 128;
    int tid = threadIdx.x, w = tid >> 5, lane = tid & 31;
    int gr = lane >> 2, cq = lane & 3;
    int mat = lane >> 3, rr = lane & 7;

    const bf16* qh_p = qh + ((size_t)h * Nn_TOK + qbase) * DH;
    const bf16* kh_p = kh + (size_t)h * Nn_TOK * DH;
    const bf16* vh_p = vth + (size_t)h * DH * Nn_TOK;
    const bf16* vl_p = vtl + (size_t)h * DH * Nn_TOK;

    // ---- stage Q (hi only), extract fragments ----
    {
        int r = tid >> 1, half = tid & 1;
        const uint4* s0 = reinterpret_cast<const uint4*>(qh_p + r * DH + half * 32);
        uint4* d0 = reinterpret_cast<uint4*>(smemc + r * 144 + half * 64);
#pragma unroll
        for (int c = 0; c < 4; c++) d0[c] = s0[c];
    }
    __syncthreads();
    uint32_t qfh[4][4];
#pragma unroll
    for (int ks = 0; ks < 4; ks++) {
        uint32_t ra = (uint32_t)(16 * w + (mat & 1) * 8 + rr) * AST144 + ks * 32 + (mat >> 1) * 16;
        ldsm4(qfh[ks], sb + ra);
    }
    __syncthreads();

    auto load_tile = [&](int kt, int s) {
        int k0 = kt * 64;
        uint32_t base = sb + s * ASTAGE;
#pragma unroll
        for (int l = 0; l < 2; l++) {
            int lin = tid + l * 256;
            int r = lin >> 3, ch = lin & 7;
            cp16(base + r * 144 + ch * 16, kh_p + (size_t)(k0 + r) * DH + ch * 8);
            cp16(base + ATILE + r * 144 + ch * 16, vh_p + (size_t)r * Nn_TOK + k0 + ch * 8);
            cp16(base + 2 * ATILE + r * 144 + ch * 16, vl_p + (size_t)r * Nn_TOK + k0 + ch * 8);
        }
    };

    load_tile(0, 0); cp_commit();
    load_tile(1, 1); cp_commit();

    float O[8][4];
#pragma unroll
    for (int a = 0; a < 8; a++)
#pragma unroll
        for (int b = 0; b < 4; b++) O[a][b] = 0.f;
    float m0 = -1e30f, m1 = -1e30f, l0 = 0.f, l1 = 0.f;

    int row0 = qbase + 16 * w + gr;
    int row1 = row0 + 8;
    int tq0 = row0 / Ss, tq1 = row1 / Ss;

    const int NT = Nn_TOK / 64;
    for (int kt = 0; kt < NT; kt++) {
        int s = kt % 3;
        cp_wait1();
        __syncthreads();
        uint32_t K0 = sb + s * ASTAGE;
        uint32_t V0 = K0 + ATILE, V1 = K0 + 2 * ATILE;

        float S[8][4];
#pragma unroll
        for (int a = 0; a < 8; a++)
#pragma unroll
            for (int b = 0; b < 4; b++) S[a][b] = 0.f;
#pragma unroll
        for (int ks = 0; ks < 4; ks++) {
#pragma unroll
            for (int ntp = 0; ntp < 4; ntp++) {
                uint32_t rb = (uint32_t)(16 * ntp + (mat >> 1) * 8 + rr) * AST144
                            + ks * 32 + (mat & 1) * 16;
                uint32_t bh[4];
                ldsm4(bh, K0 + rb);
                mma16816(S[2 * ntp], qfh[ks], bh[0], bh[1]);
                mma16816(S[2 * ntp + 1], qfh[ks], bh[2], bh[3]);
            }
        }

        // ---- mask + online softmax (log2 domain) ----
        int k0 = kt * 64;
        int tk0c = k0 / Ss;
        int change = (tk0c + 1) * Ss - k0;
        int m00 = mask[tq0 * Tt + tk0c];
        int m10 = mask[tq1 * Tt + tk0c];
        int m01 = (change < 64) ? mask[tq0 * Tt + tk0c + 1] : 1;
        int m11 = (change < 64) ? mask[tq1 * Tt + tk0c + 1] : 1;
        float b00 = m00 ? 0.f : -1e30f, b01 = m01 ? 0.f : -1e30f;
        float b10 = m10 ? 0.f : -1e30f, b11 = m11 ? 0.f : -1e30f;

        float mx0 = -1e30f, mx1 = -1e30f;
#pragma unroll
        for (int nt = 0; nt < 8; nt++) {
            int colb = 8 * nt + 2 * cq;
            float bi0 = (colb >= change) ? b01 : b00;
            float bi1 = (colb >= change) ? b11 : b10;
            S[nt][0] = S[nt][0] * SC2 + bi0;
            S[nt][1] = S[nt][1] * SC2 + bi0;
            S[nt][2] = S[nt][2] * SC2 + bi1;
            S[nt][3] = S[nt][3] * SC2 + bi1;
            mx0 = fmaxf(mx0, fmaxf(S[nt][0], S[nt][1]));
            mx1 = fmaxf(mx1, fmaxf(S[nt][2], S[nt][3]));
        }
        mx0 = fmaxf(mx0, __shfl_xor_sync(0xffffffffu, mx0, 1));
        mx0 = fmaxf(mx0, __shfl_xor_sync(0xffffffffu, mx0, 2));
        mx1 = fmaxf(mx1, __shfl_xor_sync(0xffffffffu, mx1, 1));
        mx1 = fmaxf(mx1, __shfl_xor_sync(0xffffffffu, mx1, 2));
        float mn0 = fmaxf(m0, mx0), mn1 = fmaxf(m1, mx1);
        float al0 = exp2f(m0 - mn0), al1 = exp2f(m1 - mn1);

        float rs0 = 0.f, rs1 = 0.f;
#pragma unroll
        for (int nt = 0; nt < 8; nt++) {
            S[nt][0] = exp2f(S[nt][0] - mn0);
            S[nt][1] = exp2f(S[nt][1] - mn0);
            S[nt][2] = exp2f(S[nt][2] - mn1);
            S[nt][3] = exp2f(S[nt][3] - mn1);
            rs0 += S[nt][0] + S[nt][1];
            rs1 += S[nt][2] + S[nt][3];
        }
        rs0 += __shfl_xor_sync(0xffffffffu, rs0, 1);
        rs0 += __shfl_xor_sync(0xffffffffu, rs0, 2);
        rs1 += __shfl_xor_sync(0xffffffffu, rs1, 1);
        rs1 += __shfl_xor_sync(0xffffffffu, rs1, 2);
        l0 = l0 * al0 + rs0;
        l1 = l1 * al1 + rs1;
        m0 = mn0; m1 = mn1;
        // skip O rescale when both alphas are exactly 1 (max unchanged) —
        // uniform across the 4-thread row group, so no intra-group divergence.
        if (al0 != 1.0f || al1 != 1.0f) {
#pragma unroll
            for (int nt = 0; nt < 8; nt++) {
                O[nt][0] *= al0; O[nt][1] *= al0;
                O[nt][2] *= al1; O[nt][3] *= al1;
            }
        }

        uint32_t pa[4][4];
#pragma unroll
        for (int t = 0; t < 4; t++) {
            pa[t][0] = packbf(S[2 * t][0], S[2 * t][1]);
            pa[t][1] = packbf(S[2 * t][2], S[2 * t][3]);
            pa[t][2] = packbf(S[2 * t + 1][0], S[2 * t + 1][1]);
            pa[t][3] = packbf(S[2 * t + 1][2], S[2 * t + 1][3]);
        }

#pragma unroll
        for (int t = 0; t < 4; t++) {
#pragma unroll
            for (int ntp = 0; ntp < 4; ntp++) {
                uint32_t rv = (uint32_t)(16 * ntp + (mat >> 1) * 8 + rr) * AST144
                            + t * 32 + (mat & 1) * 16;
                uint32_t vh[4], vl[4];
                ldsm4(vh, V0 + rv);
                ldsm4(vl, V1 + rv);
                mma16816(O[2 * ntp], pa[t], vh[0], vh[1]);
                mma16816(O[2 * ntp], pa[t], vl[0], vl[1]);
                mma16816(O[2 * ntp + 1], pa[t], vh[2], vh[3]);
                mma16816(O[2 * ntp + 1], pa[t], vl[2], vl[3]);
            }
        }
        if (kt + 2 < NT) load_tile(kt + 2, (kt + 2) % 3);
        cp_commit();
    }

    float inv0 = 1.0f / l0, inv1 = 1.0f / l1;
#pragma unroll
    for (int nt = 0; nt < 8; nt++) {
        int col = h * DH + 8 * nt + 2 * cq;
        float v0 = O[nt][0] * inv0, v1 = O[nt][1] * inv0;
        float v2 = O[nt][2] * inv1, v3 = O[nt][3] * inv1;
        bf16 h0, lo0, h1, lo1;
        split2(v0, h0, lo0); split2(v1, h1, lo1);
        __nv_bfloat162 hh; hh.x = h0; hh.y = h1;
        __nv_bfloat162 ll; ll.x = lo0; ll.y = lo1;
        *reinterpret_cast<uint32_t*>(&oh[(size_t)row0 * INNER + col]) = *reinterpret_cast<uint32_t*>(&hh);
        *reinterpret_cast<uint32_t*>(&ol[(size_t)row0 * INNER + col]) = *reinterpret_cast<uint32_t*>(&ll);
        split2(v2, h0, lo0); split2(v3, h1, lo1);
        hh.x = h0; hh.y = h1; ll.x = lo0; ll.y = lo1;
        *reinterpret_cast<uint32_t*>(&oh[(size_t)row1 * INNER + col]) = *reinterpret_cast<uint32_t*>(&hh);
        *reinterpret_cast<uint32_t*>(&ol[(size_t)row1 * INNER + col]) = *reinterpret_cast<uint32_t*>(&ll);
    }
}

// ---------------- host orchestration ----------------
extern "C" void kernel_launch(void* const* d_in, const int* in_sizes, int n_in,
                              void* d_out, int out_size) {
    const float* x        = (const float*)d_in[0];
    const float* y        = (const float*)d_in[1];
    const int*   mask     = (const int*)  d_in[2];
    const float* normx_g  = (const float*)d_in[3];
    const float* normx_b  = (const float*)d_in[4];
    const float* normy_g  = (const float*)d_in[5];
    const float* normy_b  = (const float*)d_in[6];
    const float* wq       = (const float*)d_in[7];
    const float* wk       = (const float*)d_in[8];
    const float* wv       = (const float*)d_in[9];
    const float* temp_pos = (const float*)d_in[10];
    const float* gate_w   = (const float*)d_in[11];
    const float* gate_b   = (const float*)d_in[12];
    const float* out_w    = (const float*)d_in[13];
    const float* out_b    = (const float*)d_in[14];
    const float* ffn_g    = (const float*)d_in[15];
    const float* ffn_b    = (const float*)d_in[16];
    const float* w1       = (const float*)d_in[17];
    const float* b1       = (const float*)d_in[18];
    const float* w2       = (const float*)d_in[19];
    const float* b2       = (const float*)d_in[20];
    float* out = (float*)d_out;

#define SYM(v, s) cudaGetSymbolAddress((void**)&v, s)
    float *p_xt, *p_yt, *p_proj, *p_qk, *p_v, *p_rc, *p_rs;
    bf16 *p_xn_h, *p_xn_l, *p_yn_h, *p_yn_l, *p_ao_h, *p_ao_l, *p_h_h, *p_h_l;
    bf16 *p_qh, *p_kh, *p_vth, *p_vtl;
    bf16 *p_wqkt_h, *p_wqkt_l, *p_wvt_h, *p_wvt_l;
    bf16 *p_owt_h, *p_owt_l, *p_w1t_h, *p_w1t_l, *p_w2t_h, *p_w2t_l;
    SYM(p_xt, g_xt); SYM(p_yt, g_yt); SYM(p_proj, g_proj);
    SYM(p_qk, g_qk); SYM(p_v, g_v); SYM(p_rc, g_rcos); SYM(p_rs, g_rsin);
    SYM(p_xn_h, g_xn_h); SYM(p_xn_l, g_xn_l); SYM(p_yn_h, g_yn_h); SYM(p_yn_l, g_yn_l);
    SYM(p_ao_h, g_ao_h); SYM(p_ao_l, g_ao_l); SYM(p_h_h, g_h_h); SYM(p_h_l, g_h_l);
    SYM(p_qh, g_qh); SYM(p_kh, g_kh);
    SYM(p_vth, g_vth); SYM(p_vtl, g_vtl);
    SYM(p_wqkt_h, g_wqkt_h); SYM(p_wqkt_l, g_wqkt_l);
    SYM(p_wvt_h, g_wvt_h); SYM(p_wvt_l, g_wvt_l);
    SYM(p_owt_h, g_owt_h); SYM(p_owt_l, g_owt_l);
    SYM(p_w1t_h, g_w1t_h); SYM(p_w1t_l, g_w1t_l);
    SYM(p_w2t_h, g_w2t_h); SYM(p_w2t_l, g_w2t_l);
#undef SYM

    static bool attr_set = false;
    if (!attr_set) {
        cudaFuncSetAttribute(gemm_mma<128>, cudaFuncAttributeMaxDynamicSharedMemorySize, GEMM_SMEM128);
        cudaFuncSetAttribute(gemm_mma<64>, cudaFuncAttributeMaxDynamicSharedMemorySize, GEMM_SMEM64);
        cudaFuncSetAttribute(attn_mma, cudaFuncAttributeMaxDynamicSharedMemorySize, ATTN_SMEM);
        attr_set = true;
    }

    pack_in_kernel<<<dim3(Ss / 16, Cc / 64, Tt), 256>>>(x, y, p_xt, p_yt);
    rope_tab<<<(Nn_TOK * 32 + 255) / 256, 256>>>(p_rc, p_rs);

    for (int i = 0; i < DEPTH; i++) {
        const float* wq_i = wq + (size_t)i * Cc * INNER;
        const float* wk_i = wk + (size_t)i * Cc * INNER;
        const float* wv_i = wv + (size_t)i * Cc * INNER;
        const float* tp_i = temp_pos + (size_t)i * MAXT * Cc;
        const float* ow_i = out_w + (size_t)i * INNER * Cc;
        const float* ob_i = out_b + (size_t)i * Cc;
        const float* gw_i = gate_w + (size_t)i * Cc;
        const float* gb_i = gate_b + i;
        const float* w1_i = w1 + (size_t)i * Cc * MLP;
        const float* b1_i = b1 + (size_t)i * MLP;
        const float* w2_i = w2 + (size_t)i * MLP * Cc;
        const float* b2_i = b2 + (size_t)i * Cc;

        ln2_kernel<<<dim3(Nn_TOK, 2), 128>>>(p_xt, p_yt, p_xn_h, p_xn_l, p_yn_h, p_yn_l,
                                             normx_g + i * Cc, normx_b + i * Cc,
                                             normy_g + i * Cc, normy_b + i * Cc, tp_i);
        tsplit_qkv<<<dim3(INNER / 64, Cc / 64, 3), 256>>>(wq_i, wk_i, wv_i,
                                                          p_wqkt_h, p_wqkt_l, p_wvt_h, p_wvt_l);

        dim3 gv(INNER / 128, Nn_TOK / 128);
        gemm_mma<128><<<gv, 256, GEMM_SMEM128>>>(p_yn_h, p_yn_l, p_wvt_h, p_wvt_l,
                                                 nullptr, nullptr, p_v, nullptr, nullptr, INNER, Cc, 0);
        dim3 gqk(QKN / 128, Nn_TOK / 128);
        gemm_mma<128><<<gqk, 256, GEMM_SMEM128>>>(p_xn_h, p_xn_l, p_wqkt_h, p_wqkt_l,
                                                  nullptr, nullptr, p_qk, nullptr, nullptr, QKN, Cc, 0);

        vt_split<<<dim3(Nn_TOK / 64, HEADS), 256>>>(p_v, p_vth, p_vtl);
        rope_split<<<(Nn_TOK * HEADS * 4 + 255) / 256, 256>>>(p_qk, p_rc, p_rs, p_qh, p_kh);
        tsplit3<<<640, 256>>>(ow_i, w1_i, w2_i, p_owt_h, p_owt_l, p_w1t_h, p_w1t_l, p_w2t_h, p_w2t_l);

        dim3 ga(Nn_TOK / 128, HEADS);
        attn_mma<<<ga, 256, ATTN_SMEM>>>(p_qh, p_kh, p_vth, p_vtl, mask, p_ao_h, p_ao_l);

        dim3 gp(Cc / 64, Nn_TOK / 128);
        gemm_mma<64><<<gp, 256, GEMM_SMEM64>>>(p_ao_h, p_ao_l, p_owt_h, p_owt_l,
                                               ob_i, nullptr, p_proj, nullptr, nullptr, Cc, INNER, 0);

        gate_ln_kernel<<<Nn_TOK, 128>>>(p_proj, gw_i, gb_i, ffn_g + i * Cc, ffn_b + i * Cc,
                                        p_xt, p_xn_h, p_xn_l);

        dim3 g1(MLP / 128, Nn_TOK / 128);
        gemm_mma<128><<<g1, 256, GEMM_SMEM128>>>(p_xn_h, p_xn_l, p_w1t_h, p_w1t_l,
                                                 b1_i, nullptr, nullptr, p_h_h, p_h_l, MLP, Cc, 1);
        dim3 g2(Cc / 64, Nn_TOK / 128);
        gemm_mma<64><<<g2, 256, GEMM_SMEM64>>>(p_h_h, p_h_l, p_w2t_h, p_w2t_l,
                                               b2_i, p_xt, p_xt, nullptr, nullptr, Cc, MLP, 0);
    }

    pack_out_kernel<<<dim3(Ss / 16, Cc / 64, Tt), 256>>>(p_xt, out);
}

// round 16
// speedup vs baseline: 1.0241x; 1.0241x over previous
#include <cuda_runtime.h>
#include <cuda_bf16.h>
#include <math.h>
#include <stdint.h>

typedef __nv_bfloat16 bf16;

// ---------------- problem constants ----------------
#define Tt 16
#define Cc 512
#define HEADS 16
#define DH 64
#define INNER 1024   // HEADS*DH
#define MLP 2048     // 4*C
#define DEPTH 2
#define MAXT 32
#define Ss 144       // H*W
#define Nn_TOK 2304  // T*S
#define SCALE 0.125f
#define SC2 (0.125f * 1.4426950408889634f)   // SCALE * log2(e)
#define EPS 1e-5f
#define QKN 2048     // fused Q|K projection width

// ---------------- scratch (device globals; no runtime alloc) -------------
__device__ __align__(256) float g_xt[Nn_TOK * Cc];
__device__ __align__(256) float g_yt[Nn_TOK * Cc];
__device__ __align__(256) bf16  g_xn_h[Nn_TOK * Cc];
__device__ __align__(256) bf16  g_xn_l[Nn_TOK * Cc];
__device__ __align__(256) bf16  g_yn_h[Nn_TOK * Cc];
__device__ __align__(256) bf16  g_yn_l[Nn_TOK * Cc];
__device__ __align__(256) float g_proj[Nn_TOK * Cc];
__device__ __align__(256) float g_qk[Nn_TOK * QKN];
__device__ __align__(256) float g_v[Nn_TOK * INNER];
__device__ __align__(256) bf16  g_ao_h[Nn_TOK * INNER];
__device__ __align__(256) bf16  g_ao_l[Nn_TOK * INNER];
__device__ __align__(256) bf16  g_h_h[Nn_TOK * MLP];
__device__ __align__(256) bf16  g_h_l[Nn_TOK * MLP];
// rope tables
__device__ __align__(256) float g_rcos[Nn_TOK * 32];
__device__ __align__(256) float g_rsin[Nn_TOK * 32];
// per-head attention operand layouts
__device__ __align__(256) bf16 g_qh[HEADS * Nn_TOK * DH];
__device__ __align__(256) bf16 g_kh[HEADS * Nn_TOK * DH];
__device__ __align__(256) bf16 g_vth[HEADS * DH * Nn_TOK];  // [h][d][n]
__device__ __align__(256) bf16 g_vtl[HEADS * DH * Nn_TOK];
// transposed + split weights [N,K] bf16
__device__ __align__(256) bf16 g_wqkt_h[QKN * Cc];
__device__ __align__(256) bf16 g_wqkt_l[QKN * Cc];
__device__ __align__(256) bf16 g_wvt_h[INNER * Cc];
__device__ __align__(256) bf16 g_wvt_l[INNER * Cc];
__device__ __align__(256) bf16 g_owt_h[Cc * INNER];
__device__ __align__(256) bf16 g_owt_l[Cc * INNER];
__device__ __align__(256) bf16 g_w1t_h[MLP * Cc];
__device__ __align__(256) bf16 g_w1t_l[MLP * Cc];
__device__ __align__(256) bf16 g_w2t_h[Cc * MLP];
__device__ __align__(256) bf16 g_w2t_l[Cc * MLP];

// ---------------- low-level helpers ----------------
__device__ __forceinline__ uint32_t smem_u32(const void* p) {
    uint32_t a;
    asm("{ .reg .u64 t; cvta.to.shared.u64 t, %1; cvt.u32.u64 %0, t; }" : "=r"(a) : "l"(p));
    return a;
}
__device__ __forceinline__ void cp16(uint32_t dst, const void* src) {
    asm volatile("cp.async.cg.shared.global [%0], [%1], 16;" :: "r"(dst), "l"(src));
}
__device__ __forceinline__ void cp_commit() { asm volatile("cp.async.commit_group;"); }
__device__ __forceinline__ void cp_wait1() { asm volatile("cp.async.wait_group 1;"); }

__device__ __forceinline__ void mma16816(float* c, const uint32_t* a, uint32_t b0, uint32_t b1) {
    asm volatile(
        "mma.sync.aligned.m16n8k16.row.col.f32.bf16.bf16.f32 "
        "{%0,%1,%2,%3}, {%4,%5,%6,%7}, {%8,%9}, {%0,%1,%2,%3};"
        : "+f"(c[0]), "+f"(c[1]), "+f"(c[2]), "+f"(c[3])
        : "r"(a[0]), "r"(a[1]), "r"(a[2]), "r"(a[3]), "r"(b0), "r"(b1));
}
__device__ __forceinline__ void ldsm4(uint32_t* r, uint32_t addr) {
    asm volatile("ldmatrix.sync.aligned.m8n8.x4.shared.b16 {%0,%1,%2,%3}, [%4];"
                 : "=r"(r[0]), "=r"(r[1]), "=r"(r[2]), "=r"(r[3]) : "r"(addr));
}
__device__ __forceinline__ uint32_t packbf(float x, float y) {
    __nv_bfloat162 t = __float22bfloat162_rn(make_float2(x, y));
    return *reinterpret_cast<uint32_t*>(&t);
}
__device__ __forceinline__ void split2(float v, bf16& h, bf16& l) {
    h = __float2bfloat16(v);
    l = __float2bfloat16(v - __bfloat162float(h));
}
// fast GELU: tanh(y) = 1 - 2/(1+exp(2y)); fast exp + fast divide.
__device__ __forceinline__ float gelu_fast(float x) {
    const float cg = 0.7978845608028654f;
    float y = cg * (x + 0.044715f * x * x * x);
    float t = 1.0f - __fdividef(2.0f, 1.0f + __expf(2.0f * y));
    return 0.5f * x * (1.0f + t);
}

// ---------------- pack: x[T,C,S] -> xt[T*S,C] (tiled transpose) ----------
__global__ void pack_in_kernel(const float* __restrict__ x, const float* __restrict__ y,
                               float* __restrict__ xt, float* __restrict__ yt) {
    __shared__ float sm[16][68];
    int sb = blockIdx.x * 16, cb = blockIdx.y * 64, t = blockIdx.z;
    int tid = threadIdx.x;
    int sl = tid & 15, cl = tid >> 4;
    int cl2 = tid & 63, sl2 = tid >> 6;

    const float* srcs[2] = { x, y };
    float* dsts[2] = { xt, yt };
#pragma unroll
    for (int a = 0; a < 2; a++) {
#pragma unroll
        for (int i = 0; i < 4; i++)
            sm[sl][cl + 16 * i] = srcs[a][((size_t)t * Cc + cb + cl + 16 * i) * Ss + sb + sl];
        __syncthreads();
#pragma unroll
        for (int p = 0; p < 4; p++)
            dsts[a][((size_t)t * Ss + sb + sl2 + 4 * p) * Cc + cb + cl2] = sm[sl2 + 4 * p][cl2];
        __syncthreads();
    }
}
// xt[T*S,C] -> out[T,C,S]
__global__ void pack_out_kernel(const float* __restrict__ xt, float* __restrict__ out) {
    __shared__ float sm[16][68];
    int sb = blockIdx.x * 16, cb = blockIdx.y * 64, t = blockIdx.z;
    int tid = threadIdx.x;
    int cl = tid & 63, sl = tid >> 6;
    int sl2 = tid & 15, cl2 = tid >> 4;
#pragma unroll
    for (int p = 0; p < 4; p++)
        sm[sl + 4 * p][cl] = xt[((size_t)t * Ss + sb + sl + 4 * p) * Cc + cb + cl];
    __syncthreads();
#pragma unroll
    for (int i = 0; i < 4; i++)
        out[((size_t)t * Cc + cb + cl2 + 16 * i) * Ss + sb + sl2] = sm[sl2][cl2 + 16 * i];
}

// ---------------- fused x/y LayerNorm (+pos) -> bf16 hi/lo ----------
__global__ void ln2_kernel(const float* __restrict__ xin, const float* __restrict__ yin,
                           bf16* __restrict__ xh, bf16* __restrict__ xl,
                           bf16* __restrict__ yh, bf16* __restrict__ yl,
                           const float* __restrict__ gx, const float* __restrict__ bx,
                           const float* __restrict__ gy, const float* __restrict__ by,
                           const float* __restrict__ pos) {
    __shared__ float red[4];
    int row = blockIdx.x;
    int which = blockIdx.y;
    const float* in = which ? yin : xin;
    bf16* oh = which ? yh : xh;
    bf16* ol = which ? yl : xl;
    const float* gamma = which ? gy : gx;
    const float* beta  = which ? by : bx;
    int tid = threadIdx.x;
    const float* x = in + (size_t)row * Cc;

    float v[4];
    float s = 0.f;
#pragma unroll
    for (int l = 0; l < 4; l++) { v[l] = x[tid + l * 128]; s += v[l]; }
#pragma unroll
    for (int o = 16; o > 0; o >>= 1) s += __shfl_xor_sync(0xffffffffu, s, o);
    int warp = tid >> 5, lane = tid & 31;
    if (lane == 0) red[warp] = s;
    __syncthreads();
    float mean = (red[0] + red[1] + red[2] + red[3]) * (1.0f / Cc);
    __syncthreads();
    float sq = 0.f;
#pragma unroll
    for (int l = 0; l < 4; l++) { float d = v[l] - mean; sq += d * d; }
#pragma unroll
    for (int o = 16; o > 0; o >>= 1) sq += __shfl_xor_sync(0xffffffffu, sq, o);
    if (lane == 0) red[warp] = sq;
    __syncthreads();
    float var = (red[0] + red[1] + red[2] + red[3]) * (1.0f / Cc);
    float inv = rsqrtf(var + EPS);

    int t = row / Ss;
#pragma unroll
    for (int l = 0; l < 4; l++) {
        int c = tid + l * 128;
        float val = (v[l] - mean) * inv * gamma[c] + beta[c] + pos[t * Cc + c];
        bf16 h, lo;
        split2(val, h, lo);
        oh[(size_t)row * Cc + c] = h;
        ol[(size_t)row * Cc + c] = lo;
    }
}

// ---------------- fused gate+residual+FFN-LN ----------------
__global__ void gate_ln_kernel(const float* __restrict__ proj,
                               const float* __restrict__ gw, const float* __restrict__ gb,
                               const float* __restrict__ gamma, const float* __restrict__ beta,
                               float* __restrict__ xt, bf16* __restrict__ oh, bf16* __restrict__ ol) {
    __shared__ float red[4];
    int row = blockIdx.x;
    int tid = threadIdx.x;
    int warp = tid >> 5, lane = tid & 31;
    const float* p = proj + (size_t)row * Cc;
    float* xr = xt + (size_t)row * Cc;

    float pv[4], xv[4];
    float s = 0.f;
#pragma unroll
    for (int l = 0; l < 4; l++) {
        int c = tid + l * 128;
        pv[l] = p[c];
        xv[l] = xr[c];
        s += pv[l] * gw[c];
    }
#pragma unroll
    for (int o = 16; o > 0; o >>= 1) s += __shfl_xor_sync(0xffffffffu, s, o);
    if (lane == 0) red[warp] = s;
    __syncthreads();
    float dot = red[0] + red[1] + red[2] + red[3];
    float g = 1.0f / (1.0f + __expf(-(dot + gb[0])));
    __syncthreads();

    float sum = 0.f;
#pragma unroll
    for (int l = 0; l < 4; l++) { xv[l] += pv[l] * g; sum += xv[l]; }
#pragma unroll
    for (int o = 16; o > 0; o >>= 1) sum += __shfl_xor_sync(0xffffffffu, sum, o);
    if (lane == 0) red[warp] = sum;
    __syncthreads();
    float mean = (red[0] + red[1] + red[2] + red[3]) * (1.0f / Cc);
    __syncthreads();
    float sq = 0.f;
#pragma unroll
    for (int l = 0; l < 4; l++) { float d = xv[l] - mean; sq += d * d; }
#pragma unroll
    for (int o = 16; o > 0; o >>= 1) sq += __shfl_xor_sync(0xffffffffu, sq, o);
    if (lane == 0) red[warp] = sq;
    __syncthreads();
    float var = (red[0] + red[1] + red[2] + red[3]) * (1.0f / Cc);
    float inv = rsqrtf(var + EPS);

#pragma unroll
    for (int l = 0; l < 4; l++) {
        int c = tid + l * 128;
        xr[c] = xv[l];
        float val = (xv[l] - mean) * inv * gamma[c] + beta[c];
        bf16 h, lo;
        split2(val, h, lo);
        oh[(size_t)row * Cc + c] = h;
        ol[(size_t)row * Cc + c] = lo;
    }
}

// ---------------- transpose + split body ----------------
__device__ __forceinline__ void tsplit_body(const float* __restrict__ W, bf16* __restrict__ hi,
                                            bf16* __restrict__ lo, int K, int N,
                                            int nb, int kb, int tid) {
    __shared__ float t[64][65];
    int kr = tid >> 4;
    int c4 = tid & 15;
#pragma unroll
    for (int i = 0; i < 4; i++) {
        int k = kr + 16 * i;
        float4 v = *reinterpret_cast<const float4*>(&W[(size_t)(kb + k) * N + nb + c4 * 4]);
        t[c4 * 4 + 0][k] = v.x; t[c4 * 4 + 1][k] = v.y;
        t[c4 * 4 + 2][k] = v.z; t[c4 * 4 + 3][k] = v.w;
    }
    __syncthreads();
    int n = tid >> 2;
    int k0 = (tid & 3) * 16;
    uint32_t hbuf[8], lbuf[8];
#pragma unroll
    for (int j = 0; j < 8; j++) {
        float v0 = t[n][k0 + 2 * j], v1 = t[n][k0 + 2 * j + 1];
        bf16 h0, l0, h1, l1;
        split2(v0, h0, l0); split2(v1, h1, l1);
        __nv_bfloat162 hh; hh.x = h0; hh.y = h1;
        __nv_bfloat162 ll; ll.x = l0; ll.y = l1;
        hbuf[j] = *reinterpret_cast<uint32_t*>(&hh);
        lbuf[j] = *reinterpret_cast<uint32_t*>(&ll);
    }
    size_t o = (size_t)(nb + n) * K + kb + k0;
    *reinterpret_cast<uint4*>(&hi[o])     = *reinterpret_cast<uint4*>(&hbuf[0]);
    *reinterpret_cast<uint4*>(&hi[o + 8]) = *reinterpret_cast<uint4*>(&hbuf[4]);
    *reinterpret_cast<uint4*>(&lo[o])     = *reinterpret_cast<uint4*>(&lbuf[0]);
    *reinterpret_cast<uint4*>(&lo[o + 8]) = *reinterpret_cast<uint4*>(&lbuf[4]);
}

// fused QKV weight split: z=0 wq, z=1 wk (into wqkt at offset), z=2 wv
__global__ void tsplit_qkv(const float* __restrict__ wq, const float* __restrict__ wk,
                           const float* __restrict__ wv,
                           bf16* __restrict__ qkt_h, bf16* __restrict__ qkt_l,
                           bf16* __restrict__ vt_h, bf16* __restrict__ vt_l) {
    int z = blockIdx.z;
    const float* W = (z == 0) ? wq : (z == 1) ? wk : wv;
    bf16* hi = (z == 0) ? qkt_h : (z == 1) ? qkt_h + (size_t)INNER * Cc : vt_h;
    bf16* lo = (z == 0) ? qkt_l : (z == 1) ? qkt_l + (size_t)INNER * Cc : vt_l;
    tsplit_body(W, hi, lo, Cc, INNER, blockIdx.x * 64, blockIdx.y * 64, threadIdx.x);
}

// fused ow/w1/w2 weight split: 1-D grid of 128+256+256 = 640 blocks
__global__ void tsplit3(const float* __restrict__ ow, const float* __restrict__ w1,
                        const float* __restrict__ w2,
                        bf16* __restrict__ owh, bf16* __restrict__ owl,
                        bf16* __restrict__ w1h, bf16* __restrict__ w1l,
                        bf16* __restrict__ w2h, bf16* __restrict__ w2l) {
    int b = blockIdx.x;
    const float* W; bf16 *hi, *lo; int K, N, lb;
    if (b < 128)      { W = ow; hi = owh; lo = owl; K = INNER; N = Cc;  lb = b; }
    else if (b < 384) { W = w1; hi = w1h; lo = w1l; K = Cc;    N = MLP; lb = b - 128; }
    else              { W = w2; hi = w2h; lo = w2l; K = MLP;   N = Cc;  lb = b - 384; }
    int nT = N / 64;
    tsplit_body(W, hi, lo, K, N, (lb % nT) * 64, (lb / nT) * 64, threadIdx.x);
}

// ---------------- mma.sync bf16 GEMM (hi/lo split, ldmatrix, 3-stage) -----
#define GROW80 80
#define GBUF_A (128 * 80)

template <int BN>
__global__ void gemm_mma(const bf16* __restrict__ Ah, const bf16* __restrict__ Al,
                         const bf16* __restrict__ Bh, const bf16* __restrict__ Bl,
                         const float* __restrict__ bias, const float* __restrict__ resid,
                         float* __restrict__ outF, bf16* __restrict__ outH, bf16* __restrict__ outL,
                         int Nc, int K, int act) {
    constexpr int WM = (BN == 128) ? 2 : 4;
    constexpr int MT = (BN == 128) ? 4 : 2;
    constexpr int GBUF_B = BN * 80;
    constexpr int GSTAGE = 2 * GBUF_A + 2 * GBUF_B;

    extern __shared__ char smemc[];
    uint32_t sb = smem_u32(smemc);
    int tid = threadIdx.x, wid = tid >> 5, lane = tid & 31;
    int gr = lane >> 2, cq = lane & 3;
    int mat = lane >> 3, rr = lane & 7;
    int wm = wid % WM, wn = wid / WM;
    int rowBase = blockIdx.y * 128, colBase = blockIdx.x * BN;
    int nc = K >> 5;

    const bf16* srcs[4] = { Ah + (size_t)rowBase * K, Al + (size_t)rowBase * K,
                            Bh + (size_t)colBase * K, Bl + (size_t)colBase * K };

    auto load_stage = [&](int kc, int s) {
        uint32_t base = sb + s * GSTAGE;
#pragma unroll
        for (int arr = 0; arr < 4; arr++) {
            int rows = (arr < 2) ? 128 : BN;
            const bf16* src = srcs[arr] + kc * 32;
            uint32_t dstb = base + ((arr < 2) ? arr * GBUF_A : 2 * GBUF_A + (arr - 2) * GBUF_B);
            for (int l = 0; l < rows * 4 / 256; l++) {
                int lin = tid + l * 256;
                int r = lin >> 2, ch = lin & 3;
                cp16(dstb + r * 80 + ch * 16, src + (size_t)r * K + ch * 8);
            }
        }
    };

    load_stage(0, 0); cp_commit();
    load_stage(1, 1); cp_commit();

    float acc[MT][4][4];
#pragma unroll
    for (int a = 0; a < MT; a++)
#pragma unroll
        for (int b = 0; b < 4; b++)
#pragma unroll
            for (int c = 0; c < 4; c++) acc[a][b][c] = 0.f;

    for (int kc = 0; kc < nc; kc++) {
        int s = kc % 3;
        cp_wait1();
        __syncthreads();
        uint32_t A0 = sb + s * GSTAGE, A1 = A0 + GBUF_A;
        uint32_t B0 = A0 + 2 * GBUF_A, B1 = B0 + GBUF_B;
#pragma unroll
        for (int ks = 0; ks < 2; ks++) {
            uint32_t af[2][MT][4];
#pragma unroll
            for (int mt = 0; mt < MT; mt++) {
                uint32_t ra = (uint32_t)(16 * MT * wm + 16 * mt + (mat & 1) * 8 + rr) * GROW80
                            + ks * 32 + (mat >> 1) * 16;
                ldsm4(af[0][mt], A0 + ra);
                ldsm4(af[1][mt], A1 + ra);
            }
#pragma unroll
            for (int ntp = 0; ntp < 2; ntp++) {
                uint32_t rb = (uint32_t)(32 * wn + 16 * ntp + (mat >> 1) * 8 + rr) * GROW80
                            + ks * 32 + (mat & 1) * 16;
                uint32_t bh[4], bl[4];
                ldsm4(bh, B0 + rb);
                ldsm4(bl, B1 + rb);
#pragma unroll
                for (int mt = 0; mt < MT; mt++) {
                    mma16816(acc[mt][2 * ntp], af[0][mt], bh[0], bh[1]);
                    mma16816(acc[mt][2 * ntp], af[0][mt], bl[0], bl[1]);
                    mma16816(acc[mt][2 * ntp], af[1][mt], bh[0], bh[1]);
                    mma16816(acc[mt][2 * ntp + 1], af[0][mt], bh[2], bh[3]);
                    mma16816(acc[mt][2 * ntp + 1], af[0][mt], bl[2], bl[3]);
                    mma16816(acc[mt][2 * ntp + 1], af[1][mt], bh[2], bh[3]);
                }
            }
        }
        if (kc + 2 < nc) load_stage(kc + 2, (kc + 2) % 3);
        cp_commit();
    }

#pragma unroll
    for (int mt = 0; mt < MT; mt++) {
#pragma unroll
        for (int nt = 0; nt < 4; nt++) {
            int col = colBase + 32 * wn + 8 * nt + 2 * cq;
#pragma unroll
            for (int half = 0; half < 2; half++) {
                int row = rowBase + 16 * MT * wm + 16 * mt + gr + 8 * half;
                float v0 = acc[mt][nt][2 * half + 0];
                float v1 = acc[mt][nt][2 * half + 1];
                if (bias) { v0 += bias[col]; v1 += bias[col + 1]; }
                if (resid) {
                    float2 rv = *reinterpret_cast<const float2*>(&resid[(size_t)row * Nc + col]);
                    v0 += rv.x; v1 += rv.y;
                }
                if (act == 1) {
                    v0 = gelu_fast(v0);
                    v1 = gelu_fast(v1);
                }
                if (outF)
                    *reinterpret_cast<float2*>(&outF[(size_t)row * Nc + col]) = make_float2(v0, v1);
                if (outH) {
                    bf16 h0, l0, h1, l1;
                    split2(v0, h0, l0);
                    split2(v1, h1, l1);
                    __nv_bfloat162 hh; hh.x = h0; hh.y = h1;
                    __nv_bfloat162 ll; ll.x = l0; ll.y = l1;
                    *reinterpret_cast<uint32_t*>(&outH[(size_t)row * Nc + col]) =
                        *reinterpret_cast<uint32_t*>(&hh);
                    *reinterpret_cast<uint32_t*>(&outL[(size_t)row * Nc + col]) =
                        *reinterpret_cast<uint32_t*>(&ll);
                }
            }
        }
    }
}

#define GEMM_SMEM128 (3 * (2 * GBUF_A + 2 * 128 * 80))  // 122880
#define GEMM_SMEM64  (3 * (2 * GBUF_A + 2 * 64 * 80))   // 92160

// ---------------- rope table ----------------
__global__ void rope_tab(float* __restrict__ rc, float* __restrict__ rs) {
    int idx = blockIdx.x * blockDim.x + threadIdx.x;
    if (idx >= Nn_TOK * 32) return;
    int j = idx & 31, n = idx >> 5;
    const float LOG1E4_OVER32 = 9.210340371976184f / 32.0f;
    float f = __expf(-(float)j * LOG1E4_OVER32);
    float ang = (float)n * f;
    rc[idx] = cosf(ang);
    rs[idx] = sinf(ang);
}

// ---------------- RoPE + pack into per-head layout (hi-only q,k) -------
__global__ void rope_split(const float* __restrict__ qk,
                           const float* __restrict__ rc, const float* __restrict__ rs,
                           bf16* __restrict__ qh_, bf16* __restrict__ kh_) {
    int idx = blockIdx.x * blockDim.x + threadIdx.x;
    if (idx >= Nn_TOK * HEADS * 4) return;
    int j8 = idx & 3;
    int nh = idx >> 2;
    int h = nh & 15;
    int n = nh >> 4;
    int j = j8 * 8;

    float c[8], s[8], a[8], b[8], ka[8], kb[8];
    *reinterpret_cast<float4*>(c)     = *reinterpret_cast<const float4*>(&rc[n * 32 + j]);
    *reinterpret_cast<float4*>(c + 4) = *reinterpret_cast<const float4*>(&rc[n * 32 + j + 4]);
    *reinterpret_cast<float4*>(s)     = *reinterpret_cast<const float4*>(&rs[n * 32 + j]);
    *reinterpret_cast<float4*>(s + 4) = *reinterpret_cast<const float4*>(&rs[n * 32 + j + 4]);

    size_t srcq = (size_t)n * QKN + h * DH;
    size_t srck = srcq + INNER;
    *reinterpret_cast<float4*>(a)      = *reinterpret_cast<const float4*>(&qk[srcq + j]);
    *reinterpret_cast<float4*>(a + 4)  = *reinterpret_cast<const float4*>(&qk[srcq + j + 4]);
    *reinterpret_cast<float4*>(b)      = *reinterpret_cast<const float4*>(&qk[srcq + j + 32]);
    *reinterpret_cast<float4*>(b + 4)  = *reinterpret_cast<const float4*>(&qk[srcq + j + 36]);
    *reinterpret_cast<float4*>(ka)     = *reinterpret_cast<const float4*>(&qk[srck + j]);
    *reinterpret_cast<float4*>(ka + 4) = *reinterpret_cast<const float4*>(&qk[srck + j + 4]);
    *reinterpret_cast<float4*>(kb)     = *reinterpret_cast<const float4*>(&qk[srck + j + 32]);
    *reinterpret_cast<float4*>(kb + 4) = *reinterpret_cast<const float4*>(&qk[srck + j + 36]);

    size_t dst = ((size_t)h * Nn_TOK + n) * DH;
    uint32_t qh1[4], qh2[4], kh1[4], kh2[4];
#pragma unroll
    for (int i = 0; i < 4; i++) {
        float r1a = a[2 * i] * c[2 * i] - b[2 * i] * s[2 * i];
        float r1b = a[2 * i + 1] * c[2 * i + 1] - b[2 * i + 1] * s[2 * i + 1];
        float r2a = b[2 * i] * c[2 * i] + a[2 * i] * s[2 * i];
        float r2b = b[2 * i + 1] * c[2 * i + 1] + a[2 * i + 1] * s[2 * i + 1];
        qh1[i] = packbf(r1a, r1b);
        qh2[i] = packbf(r2a, r2b);

        float k1a = ka[2 * i] * c[2 * i] - kb[2 * i] * s[2 * i];
        float k1b = ka[2 * i + 1] * c[2 * i + 1] - kb[2 * i + 1] * s[2 * i + 1];
        float k2a = kb[2 * i] * c[2 * i] + ka[2 * i] * s[2 * i];
        float k2b = kb[2 * i + 1] * c[2 * i + 1] + ka[2 * i + 1] * s[2 * i + 1];
        kh1[i] = packbf(k1a, k1b);
        kh2[i] = packbf(k2a, k2b);
    }
    *reinterpret_cast<uint4*>(&qh_[dst + j])      = *reinterpret_cast<uint4*>(qh1);
    *reinterpret_cast<uint4*>(&qh_[dst + j + 32]) = *reinterpret_cast<uint4*>(qh2);
    *reinterpret_cast<uint4*>(&kh_[dst + j])      = *reinterpret_cast<uint4*>(kh1);
    *reinterpret_cast<uint4*>(&kh_[dst + j + 32]) = *reinterpret_cast<uint4*>(kh2);
}

// ---------------- V transpose + split (64x64 tiles, vectorized) ----------
// grid (Nn_TOK/64, HEADS), block 256
__global__ void vt_split(const float* __restrict__ v, bf16* __restrict__ vh_, bf16* __restrict__ vl_) {
    __shared__ float tsm[64][65];
    int n0 = blockIdx.x * 64;
    int h = blockIdx.y;
    int tid = threadIdx.x;
    int r = tid >> 4, c4 = tid & 15;
#pragma unroll
    for (int i = 0; i < 4; i++) {
        int row = r + 16 * i;
        float4 val = *reinterpret_cast<const float4*>(&v[(size_t)(n0 + row) * INNER + h * DH + c4 * 4]);
        tsm[c4 * 4 + 0][row] = val.x; tsm[c4 * 4 + 1][row] = val.y;
        tsm[c4 * 4 + 2][row] = val.z; tsm[c4 * 4 + 3][row] = val.w;
    }
    __syncthreads();
    int d = tid >> 2;
    int nn0 = (tid & 3) * 16;
    uint32_t hbuf[8], lbuf[8];
#pragma unroll
    for (int j = 0; j < 8; j++) {
        float v0 = tsm[d][nn0 + 2 * j], v1 = tsm[d][nn0 + 2 * j + 1];
        bf16 h0, l0, h1, l1;
        split2(v0, h0, l0); split2(v1, h1, l1);
        __nv_bfloat162 hh; hh.x = h0; hh.y = h1;
        __nv_bfloat162 ll; ll.x = l0; ll.y = l1;
        hbuf[j] = *reinterpret_cast<uint32_t*>(&hh);
        lbuf[j] = *reinterpret_cast<uint32_t*>(&ll);
    }
    size_t o = ((size_t)h * DH + d) * Nn_TOK + n0 + nn0;
    *reinterpret_cast<uint4*>(&vh_[o])     = *reinterpret_cast<uint4*>(&hbuf[0]);
    *reinterpret_cast<uint4*>(&vh_[o + 8]) = *reinterpret_cast<uint4*>(&hbuf[4]);
    *reinterpret_cast<uint4*>(&vl_[o])     = *reinterpret_cast<uint4*>(&lbuf[0]);
    *reinterpret_cast<uint4*>(&vl_[o + 8]) = *reinterpret_cast<uint4*>(&lbuf[4]);
}

// ---------------- flash attention via mma.sync + ldmatrix (3-stage) -------
// 128 q-rows / CTA, 256 threads. Q hi-only, K hi-only; V hi+lo. log2-domain softmax.
#define AST144 144
#define ATILE (64 * 144)
#define ASTAGE (3 * ATILE)       // Kh, Vh, Vl
#define ATTN_SMEM (3 * ASTAGE)   // 82944 B

__global__ __launch_bounds__(256)
void attn_mma(const bf16* __restrict__ qh, const bf16* __restrict__ kh,
              const bf16* __restrict__ vth, const bf16* __restrict__ vtl,
              const int* __restrict__ mask,
              bf16* __restrict__ oh, bf16* __restrict__ ol) {
    extern __shared__ char smemc[];
    uint32_t sb = smem_u32(smemc);
    int h = blockIdx.y;
    int qbase = blockIdx.x * 128;
    int tid = threadIdx.x, w = tid >> 5, lane = tid & 31;
    int gr = lane >> 2, cq = lane & 3;
    int mat = lane >> 3, rr = lane & 7;

    const bf16* qh_p = qh + ((size_t)h * Nn_TOK + qbase) * DH;
    const bf16* kh_p = kh + (size_t)h * Nn_TOK * DH;
    const bf16* vh_p = vth + (size_t)h * DH * Nn_TOK;
    const bf16* vl_p = vtl + (size_t)h * DH * Nn_TOK;

    // ---- stage Q (hi only), extract fragments ----
    {
        int r = tid >> 1, half = tid & 1;
        const uint4* s0 = reinterpret_cast<const uint4*>(qh_p + r * DH + half * 32);
        uint4* d0 = reinterpret_cast<uint4*>(smemc + r * 144 + half * 64);
#pragma unroll
        for (int c = 0; c < 4; c++) d0[c] = s0[c];
    }
    __syncthreads();
    uint32_t qfh[4][4];
#pragma unroll
    for (int ks = 0; ks < 4; ks++) {
        uint32_t ra = (uint32_t)(16 * w + (mat & 1) * 8 + rr) * AST144 + ks * 32 + (mat >> 1) * 16;
        ldsm4(qfh[ks], sb + ra);
    }
    __syncthreads();

    auto load_tile = [&](int kt, int s) {
        int k0 = kt * 64;
        uint32_t base = sb + s * ASTAGE;
#pragma unroll
        for (int l = 0; l < 2; l++) {
            int lin = tid + l * 256;
            int r = lin >> 3, ch = lin & 7;
            cp16(base + r * 144 + ch * 16, kh_p + (size_t)(k0 + r) * DH + ch * 8);
            cp16(base + ATILE + r * 144 + ch * 16, vh_p + (size_t)r * Nn_TOK + k0 + ch * 8);
            cp16(base + 2 * ATILE + r * 144 + ch * 16, vl_p + (size_t)r * Nn_TOK + k0 + ch * 8);
        }
    };

    load_tile(0, 0); cp_commit();
    load_tile(1, 1); cp_commit();

    float O[8][4];
#pragma unroll
    for (int a = 0; a < 8; a++)
#pragma unroll
        for (int b = 0; b < 4; b++) O[a][b] = 0.f;
    float m0 = -1e30f, m1 = -1e30f, l0 = 0.f, l1 = 0.f;

    int row0 = qbase + 16 * w + gr;
    int row1 = row0 + 8;
    int tq0 = row0 / Ss, tq1 = row1 / Ss;

    const int NT = Nn_TOK / 64;
    for (int kt = 0; kt < NT; kt++) {
        int s = kt % 3;
        cp_wait1();
        __syncthreads();
        uint32_t K0 = sb + s * ASTAGE;
        uint32_t V0 = K0 + ATILE, V1 = K0 + 2 * ATILE;

        float S[8][4];
#pragma unroll
        for (int a = 0; a < 8; a++)
#pragma unroll
            for (int b = 0; b < 4; b++) S[a][b] = 0.f;
#pragma unroll
        for (int ks = 0; ks < 4; ks++) {
#pragma unroll
            for (int ntp = 0; ntp < 4; ntp++) {
                uint32_t rb = (uint32_t)(16 * ntp + (mat >> 1) * 8 + rr) * AST144
                            + ks * 32 + (mat & 1) * 16;
                uint32_t bh[4];
                ldsm4(bh, K0 + rb);
                mma16816(S[2 * ntp], qfh[ks], bh[0], bh[1]);
                mma16816(S[2 * ntp + 1], qfh[ks], bh[2], bh[3]);
            }
        }

        // ---- mask + online softmax (log2 domain) ----
        int k0 = kt * 64;
        int tk0c = k0 / Ss;
        int change = (tk0c + 1) * Ss - k0;
        int m00 = mask[tq0 * Tt + tk0c];
        int m10 = mask[tq1 * Tt + tk0c];
        int m01 = (change < 64) ? mask[tq0 * Tt + tk0c + 1] : 1;
        int m11 = (change < 64) ? mask[tq1 * Tt + tk0c + 1] : 1;
        float b00 = m00 ? 0.f : -1e30f, b01 = m01 ? 0.f : -1e30f;
        float b10 = m10 ? 0.f : -1e30f, b11 = m11 ? 0.f : -1e30f;

        float mx0 = -1e30f, mx1 = -1e30f;
#pragma unroll
        for (int nt = 0; nt < 8; nt++) {
            int colb = 8 * nt + 2 * cq;
            float bi0 = (colb >= change) ? b01 : b00;
            float bi1 = (colb >= change) ? b11 : b10;
            S[nt][0] = S[nt][0] * SC2 + bi0;
            S[nt][1] = S[nt][1] * SC2 + bi0;
            S[nt][2] = S[nt][2] * SC2 + bi1;
            S[nt][3] = S[nt][3] * SC2 + bi1;
            mx0 = fmaxf(mx0, fmaxf(S[nt][0], S[nt][1]));
            mx1 = fmaxf(mx1, fmaxf(S[nt][2], S[nt][3]));
        }
        mx0 = fmaxf(mx0, __shfl_xor_sync(0xffffffffu, mx0, 1));
        mx0 = fmaxf(mx0, __shfl_xor_sync(0xffffffffu, mx0, 2));
        mx1 = fmaxf(mx1, __shfl_xor_sync(0xffffffffu, mx1, 1));
        mx1 = fmaxf(mx1, __shfl_xor_sync(0xffffffffu, mx1, 2));
        float mn0 = fmaxf(m0, mx0), mn1 = fmaxf(m1, mx1);
        float al0 = exp2f(m0 - mn0), al1 = exp2f(m1 - mn1);

        float rs0 = 0.f, rs1 = 0.f;
#pragma unroll
        for (int nt = 0; nt < 8; nt++) {
            S[nt][0] = exp2f(S[nt][0] - mn0);
            S[nt][1] = exp2f(S[nt][1] - mn0);
            S[nt][2] = exp2f(S[nt][2] - mn1);
            S[nt][3] = exp2f(S[nt][3] - mn1);
            rs0 += S[nt][0] + S[nt][1];
            rs1 += S[nt][2] + S[nt][3];
        }
        rs0 += __shfl_xor_sync(0xffffffffu, rs0, 1);
        rs0 += __shfl_xor_sync(0xffffffffu, rs0, 2);
        rs1 += __shfl_xor_sync(0xffffffffu, rs1, 1);
        rs1 += __shfl_xor_sync(0xffffffffu, rs1, 2);
        l0 = l0 * al0 + rs0;
        l1 = l1 * al1 + rs1;
        m0 = mn0; m1 = mn1;
#pragma unroll
        for (int nt = 0; nt < 8; nt++) {
            O[nt][0] *= al0; O[nt][1] *= al0;
            O[nt][2] *= al1; O[nt][3] *= al1;
        }

        uint32_t pa[4][4];
#pragma unroll
        for (int t = 0; t < 4; t++) {
            pa[t][0] = packbf(S[2 * t][0], S[2 * t][1]);
            pa[t][1] = packbf(S[2 * t][2], S[2 * t][3]);
            pa[t][2] = packbf(S[2 * t + 1][0], S[2 * t + 1][1]);
            pa[t][3] = packbf(S[2 * t + 1][2], S[2 * t + 1][3]);
        }

#pragma unroll
        for (int t = 0; t < 4; t++) {
#pragma unroll
            for (int ntp = 0; ntp < 4; ntp++) {
                uint32_t rv = (uint32_t)(16 * ntp + (mat >> 1) * 8 + rr) * AST144
                            + t * 32 + (mat & 1) * 16;
                uint32_t vh[4], vl[4];
                ldsm4(vh, V0 + rv);
                ldsm4(vl, V1 + rv);
                mma16816(O[2 * ntp], pa[t], vh[0], vh[1]);
                mma16816(O[2 * ntp], pa[t], vl[0], vl[1]);
                mma16816(O[2 * ntp + 1], pa[t], vh[2], vh[3]);
                mma16816(O[2 * ntp + 1], pa[t], vl[2], vl[3]);
            }
        }
        if (kt + 2 < NT) load_tile(kt + 2, (kt + 2) % 3);
        cp_commit();
    }

    float inv0 = 1.0f / l0, inv1 = 1.0f / l1;
#pragma unroll
    for (int nt = 0; nt < 8; nt++) {
        int col = h * DH + 8 * nt + 2 * cq;
        float v0 = O[nt][0] * inv0, v1 = O[nt][1] * inv0;
        float v2 = O[nt][2] * inv1, v3 = O[nt][3] * inv1;
        bf16 h0, lo0, h1, lo1;
        split2(v0, h0, lo0); split2(v1, h1, lo1);
        __nv_bfloat162 hh; hh.x = h0; hh.y = h1;
        __nv_bfloat162 ll; ll.x = lo0; ll.y = lo1;
        *reinterpret_cast<uint32_t*>(&oh[(size_t)row0 * INNER + col]) = *reinterpret_cast<uint32_t*>(&hh);
        *reinterpret_cast<uint32_t*>(&ol[(size_t)row0 * INNER + col]) = *reinterpret_cast<uint32_t*>(&ll);
        split2(v2, h0, lo0); split2(v3, h1, lo1);
        hh.x = h0; hh.y = h1; ll.x = lo0; ll.y = lo1;
        *reinterpret_cast<uint32_t*>(&oh[(size_t)row1 * INNER + col]) = *reinterpret_cast<uint32_t*>(&hh);
        *reinterpret_cast<uint32_t*>(&ol[(size_t)row1 * INNER + col]) = *reinterpret_cast<uint32_t*>(&ll);
    }
}

// ---------------- host orchestration ----------------
extern "C" void kernel_launch(void* const* d_in, const int* in_sizes, int n_in,
                              void* d_out, int out_size) {
    const float* x        = (const float*)d_in[0];
    const float* y        = (const float*)d_in[1];
    const int*   mask     = (const int*)  d_in[2];
    const float* normx_g  = (const float*)d_in[3];
    const float* normx_b  = (const float*)d_in[4];
    const float* normy_g  = (const float*)d_in[5];
    const float* normy_b  = (const float*)d_in[6];
    const float* wq       = (const float*)d_in[7];
    const float* wk       = (const float*)d_in[8];
    const float* wv       = (const float*)d_in[9];
    const float* temp_pos = (const float*)d_in[10];
    const float* gate_w   = (const float*)d_in[11];
    const float* gate_b   = (const float*)d_in[12];
    const float* out_w    = (const float*)d_in[13];
    const float* out_b    = (const float*)d_in[14];
    const float* ffn_g    = (const float*)d_in[15];
    const float* ffn_b    = (const float*)d_in[16];
    const float* w1       = (const float*)d_in[17];
    const float* b1       = (const float*)d_in[18];
    const float* w2       = (const float*)d_in[19];
    const float* b2       = (const float*)d_in[20];
    float* out = (float*)d_out;

#define SYM(v, s) cudaGetSymbolAddress((void**)&v, s)
    float *p_xt, *p_yt, *p_proj, *p_qk, *p_v, *p_rc, *p_rs;
    bf16 *p_xn_h, *p_xn_l, *p_yn_h, *p_yn_l, *p_ao_h, *p_ao_l, *p_h_h, *p_h_l;
    bf16 *p_qh, *p_kh, *p_vth, *p_vtl;
    bf16 *p_wqkt_h, *p_wqkt_l, *p_wvt_h, *p_wvt_l;
    bf16 *p_owt_h, *p_owt_l, *p_w1t_h, *p_w1t_l, *p_w2t_h, *p_w2t_l;
    SYM(p_xt, g_xt); SYM(p_yt, g_yt); SYM(p_proj, g_proj);
    SYM(p_qk, g_qk); SYM(p_v, g_v); SYM(p_rc, g_rcos); SYM(p_rs, g_rsin);
    SYM(p_xn_h, g_xn_h); SYM(p_xn_l, g_xn_l); SYM(p_yn_h, g_yn_h); SYM(p_yn_l, g_yn_l);
    SYM(p_ao_h, g_ao_h); SYM(p_ao_l, g_ao_l); SYM(p_h_h, g_h_h); SYM(p_h_l, g_h_l);
    SYM(p_qh, g_qh); SYM(p_kh, g_kh);
    SYM(p_vth, g_vth); SYM(p_vtl, g_vtl);
    SYM(p_wqkt_h, g_wqkt_h); SYM(p_wqkt_l, g_wqkt_l);
    SYM(p_wvt_h, g_wvt_h); SYM(p_wvt_l, g_wvt_l);
    SYM(p_owt_h, g_owt_h); SYM(p_owt_l, g_owt_l);
    SYM(p_w1t_h, g_w1t_h); SYM(p_w1t_l, g_w1t_l);
    SYM(p_w2t_h, g_w2t_h); SYM(p_w2t_l, g_w2t_l);
#undef SYM

    static bool attr_set = false;
    if (!attr_set) {
        cudaFuncSetAttribute(gemm_mma<128>, cudaFuncAttributeMaxDynamicSharedMemorySize, GEMM_SMEM128);
        cudaFuncSetAttribute(gemm_mma<64>, cudaFuncAttributeMaxDynamicSharedMemorySize, GEMM_SMEM64);
        cudaFuncSetAttribute(attn_mma, cudaFuncAttributeMaxDynamicSharedMemorySize, ATTN_SMEM);
        attr_set = true;
    }

    pack_in_kernel<<<dim3(Ss / 16, Cc / 64, Tt), 256>>>(x, y, p_xt, p_yt);
    rope_tab<<<(Nn_TOK * 32 + 255) / 256, 256>>>(p_rc, p_rs);

    for (int i = 0; i < DEPTH; i++) {
        const float* wq_i = wq + (size_t)i * Cc * INNER;
        const float* wk_i = wk + (size_t)i * Cc * INNER;
        const float* wv_i = wv + (size_t)i * Cc * INNER;
        const float* tp_i = temp_pos + (size_t)i * MAXT * Cc;
        const float* ow_i = out_w + (size_t)i * INNER * Cc;
        const float* ob_i = out_b + (size_t)i * Cc;
        const float* gw_i = gate_w + (size_t)i * Cc;
        const float* gb_i = gate_b + i;
        const float* w1_i = w1 + (size_t)i * Cc * MLP;
        const float* b1_i = b1 + (size_t)i * MLP;
        const float* w2_i = w2 + (size_t)i * MLP * Cc;
        const float* b2_i = b2 + (size_t)i * Cc;

        ln2_kernel<<<dim3(Nn_TOK, 2), 128>>>(p_xt, p_yt, p_xn_h, p_xn_l, p_yn_h, p_yn_l,
                                             normx_g + i * Cc, normx_b + i * Cc,
                                             normy_g + i * Cc, normy_b + i * Cc, tp_i);
        tsplit_qkv<<<dim3(INNER / 64, Cc / 64, 3), 256>>>(wq_i, wk_i, wv_i,
                                                          p_wqkt_h, p_wqkt_l, p_wvt_h, p_wvt_l);

        dim3 gv(INNER / 128, Nn_TOK / 128);
        gemm_mma<128><<<gv, 256, GEMM_SMEM128>>>(p_yn_h, p_yn_l, p_wvt_h, p_wvt_l,
                                                 nullptr, nullptr, p_v, nullptr, nullptr, INNER, Cc, 0);
        dim3 gqk(QKN / 128, Nn_TOK / 128);
        gemm_mma<128><<<gqk, 256, GEMM_SMEM128>>>(p_xn_h, p_xn_l, p_wqkt_h, p_wqkt_l,
                                                  nullptr, nullptr, p_qk, nullptr, nullptr, QKN, Cc, 0);

        vt_split<<<dim3(Nn_TOK / 64, HEADS), 256>>>(p_v, p_vth, p_vtl);
        rope_split<<<(Nn_TOK * HEADS * 4 + 255) / 256, 256>>>(p_qk, p_rc, p_rs, p_qh, p_kh);
        tsplit3<<<640, 256>>>(ow_i, w1_i, w2_i, p_owt_h, p_owt_l, p_w1t_h, p_w1t_l, p_w2t_h, p_w2t_l);

        dim3 ga(Nn_TOK / 128, HEADS);
        attn_mma<<<ga, 256, ATTN_SMEM>>>(p_qh, p_kh, p_vth, p_vtl, mask, p_ao_h, p_ao_l);

        dim3 gp(Cc / 64, Nn_TOK / 128);
        gemm_mma<64><<<gp, 256, GEMM_SMEM64>>>(p_ao_h, p_ao_l, p_owt_h, p_owt_l,
                                               ob_i, nullptr, p_proj, nullptr, nullptr, Cc, INNER, 0);

        gate_ln_kernel<<<Nn_TOK, 128>>>(p_proj, gw_i, gb_i, ffn_g + i * Cc, ffn_b + i * Cc,
                                        p_xt, p_xn_h, p_xn_l);

        dim3 g1(MLP / 128, Nn_TOK / 128);
        gemm_mma<128><<<g1, 256, GEMM_SMEM128>>>(p_xn_h, p_xn_l, p_w1t_h, p_w1t_l,
                                                 b1_i, nullptr, nullptr, p_h_h, p_h_l, MLP, Cc, 1);
        dim3 g2(Cc / 64, Nn_TOK / 128);
        gemm_mma<64><<<g2, 256, GEMM_SMEM64>>>(p_h_h, p_h_l, p_w2t_h, p_w2t_l,
                                               b2_i, p_xt, p_xt, nullptr, nullptr, Cc, MLP, 0);
    }

    pack_out_kernel<<<dim3(Ss / 16, Cc / 64, Tt), 256>>>(p_xt, out);
}

// round 17
// speedup vs baseline: 1.0623x; 1.0374x over previous
#include <cuda_runtime.h>
#include <cuda_bf16.h>
#include <math.h>
#include <stdint.h>

typedef __nv_bfloat16 bf16;

// ---------------- problem constants ----------------
#define Tt 16
#define Cc 512
#define HEADS 16
#define DH 64
#define INNER 1024   // HEADS*DH
#define MLP 2048     // 4*C
#define DEPTH 2
#define MAXT 32
#define Ss 144       // H*W
#define Nn_TOK 2304  // T*S
#define SCALE 0.125f
#define SC2 (0.125f * 1.4426950408889634f)   // SCALE * log2(e)
#define EPS 1e-5f
#define QKN 2048     // fused Q|K projection width

// ---------------- scratch (device globals; no runtime alloc) -------------
__device__ __align__(256) float g_xt[Nn_TOK * Cc];
__device__ __align__(256) float g_yt[Nn_TOK * Cc];
__device__ __align__(256) bf16  g_xn_h[Nn_TOK * Cc];
__device__ __align__(256) bf16  g_xn_l[Nn_TOK * Cc];
__device__ __align__(256) bf16  g_yn_h[Nn_TOK * Cc];
__device__ __align__(256) bf16  g_yn_l[Nn_TOK * Cc];
__device__ __align__(256) float g_proj[Nn_TOK * Cc];
__device__ __align__(256) float g_qk[Nn_TOK * QKN];
__device__ __align__(256) float g_v[Nn_TOK * INNER];
__device__ __align__(256) bf16  g_ao_h[Nn_TOK * INNER];
__device__ __align__(256) bf16  g_ao_l[Nn_TOK * INNER];
__device__ __align__(256) bf16  g_h_h[Nn_TOK * MLP];
__device__ __align__(256) bf16  g_h_l[Nn_TOK * MLP];
// rope tables
__device__ __align__(256) float g_rcos[Nn_TOK * 32];
__device__ __align__(256) float g_rsin[Nn_TOK * 32];
// per-head attention operand layouts
__device__ __align__(256) bf16 g_qh[HEADS * Nn_TOK * DH];
__device__ __align__(256) bf16 g_kh[HEADS * Nn_TOK * DH];
__device__ __align__(256) bf16 g_vth[HEADS * DH * Nn_TOK];  // [h][d][n]
__device__ __align__(256) bf16 g_vtl[HEADS * DH * Nn_TOK];
// transposed + split weights [N,K] bf16
__device__ __align__(256) bf16 g_wqkt_h[QKN * Cc];
__device__ __align__(256) bf16 g_wqkt_l[QKN * Cc];
__device__ __align__(256) bf16 g_wvt_h[INNER * Cc];
__device__ __align__(256) bf16 g_wvt_l[INNER * Cc];
__device__ __align__(256) bf16 g_owt_h[Cc * INNER];
__device__ __align__(256) bf16 g_owt_l[Cc * INNER];
__device__ __align__(256) bf16 g_w1t_h[MLP * Cc];
__device__ __align__(256) bf16 g_w1t_l[MLP * Cc];
__device__ __align__(256) bf16 g_w2t_h[Cc * MLP];
__device__ __align__(256) bf16 g_w2t_l[Cc * MLP];

// ---------------- low-level helpers ----------------
__device__ __forceinline__ uint32_t smem_u32(const void* p) {
    uint32_t a;
    asm("{ .reg .u64 t; cvta.to.shared.u64 t, %1; cvt.u32.u64 %0, t; }" : "=r"(a) : "l"(p));
    return a;
}
__device__ __forceinline__ void cp16(uint32_t dst, const void* src) {
    asm volatile("cp.async.cg.shared.global [%0], [%1], 16;" :: "r"(dst), "l"(src));
}
__device__ __forceinline__ void cp_commit() { asm volatile("cp.async.commit_group;"); }
__device__ __forceinline__ void cp_wait1() { asm volatile("cp.async.wait_group 1;"); }

__device__ __forceinline__ void mma16816(float* c, const uint32_t* a, uint32_t b0, uint32_t b1) {
    asm volatile(
        "mma.sync.aligned.m16n8k16.row.col.f32.bf16.bf16.f32 "
        "{%0,%1,%2,%3}, {%4,%5,%6,%7}, {%8,%9}, {%0,%1,%2,%3};"
        : "+f"(c[0]), "+f"(c[1]), "+f"(c[2]), "+f"(c[3])
        : "r"(a[0]), "r"(a[1]), "r"(a[2]), "r"(a[3]), "r"(b0), "r"(b1));
}
__device__ __forceinline__ void ldsm4(uint32_t* r, uint32_t addr) {
    asm volatile("ldmatrix.sync.aligned.m8n8.x4.shared.b16 {%0,%1,%2,%3}, [%4];"
                 : "=r"(r[0]), "=r"(r[1]), "=r"(r[2]), "=r"(r[3]) : "r"(addr));
}
__device__ __forceinline__ uint32_t packbf(float x, float y) {
    __nv_bfloat162 t = __float22bfloat162_rn(make_float2(x, y));
    return *reinterpret_cast<uint32_t*>(&t);
}
__device__ __forceinline__ void split2(float v, bf16& h, bf16& l) {
    h = __float2bfloat16(v);
    l = __float2bfloat16(v - __bfloat162float(h));
}
// fast GELU: tanh(y) = 1 - 2/(1+exp(2y)); fast exp + fast divide.
__device__ __forceinline__ float gelu_fast(float x) {
    const float cg = 0.7978845608028654f;
    float y = cg * (x + 0.044715f * x * x * x);
    float t = 1.0f - __fdividef(2.0f, 1.0f + __expf(2.0f * y));
    return 0.5f * x * (1.0f + t);
}

// ---------------- pack: x[T,C,S] -> xt[T*S,C] (tiled transpose) ----------
__global__ void pack_in_kernel(const float* __restrict__ x, const float* __restrict__ y,
                               float* __restrict__ xt, float* __restrict__ yt) {
    __shared__ float sm[16][68];
    int sb = blockIdx.x * 16, cb = blockIdx.y * 64, t = blockIdx.z;
    int tid = threadIdx.x;
    int sl = tid & 15, cl = tid >> 4;
    int cl2 = tid & 63, sl2 = tid >> 6;

    const float* srcs[2] = { x, y };
    float* dsts[2] = { xt, yt };
#pragma unroll
    for (int a = 0; a < 2; a++) {
#pragma unroll
        for (int i = 0; i < 4; i++)
            sm[sl][cl + 16 * i] = srcs[a][((size_t)t * Cc + cb + cl + 16 * i) * Ss + sb + sl];
        __syncthreads();
#pragma unroll
        for (int p = 0; p < 4; p++)
            dsts[a][((size_t)t * Ss + sb + sl2 + 4 * p) * Cc + cb + cl2] = sm[sl2 + 4 * p][cl2];
        __syncthreads();
    }
}
// xt[T*S,C] -> out[T,C,S]
__global__ void pack_out_kernel(const float* __restrict__ xt, float* __restrict__ out) {
    __shared__ float sm[16][68];
    int sb = blockIdx.x * 16, cb = blockIdx.y * 64, t = blockIdx.z;
    int tid = threadIdx.x;
    int cl = tid & 63, sl = tid >> 6;
    int sl2 = tid & 15, cl2 = tid >> 4;
#pragma unroll
    for (int p = 0; p < 4; p++)
        sm[sl + 4 * p][cl] = xt[((size_t)t * Ss + sb + sl + 4 * p) * Cc + cb + cl];
    __syncthreads();
#pragma unroll
    for (int i = 0; i < 4; i++)
        out[((size_t)t * Cc + cb + cl2 + 16 * i) * Ss + sb + sl2] = sm[sl2][cl2 + 16 * i];
}

// ---------------- fused x/y LayerNorm (+pos) -> bf16 hi/lo ----------
__global__ void ln2_kernel(const float* __restrict__ xin, const float* __restrict__ yin,
                           bf16* __restrict__ xh, bf16* __restrict__ xl,
                           bf16* __restrict__ yh, bf16* __restrict__ yl,
                           const float* __restrict__ gx, const float* __restrict__ bx,
                           const float* __restrict__ gy, const float* __restrict__ by,
                           const float* __restrict__ pos) {
    __shared__ float red[4];
    int row = blockIdx.x;
    int which = blockIdx.y;
    const float* in = which ? yin : xin;
    bf16* oh = which ? yh : xh;
    bf16* ol = which ? yl : xl;
    const float* gamma = which ? gy : gx;
    const float* beta  = which ? by : bx;
    int tid = threadIdx.x;
    const float* x = in + (size_t)row * Cc;

    float v[4];
    float s = 0.f;
#pragma unroll
    for (int l = 0; l < 4; l++) { v[l] = x[tid + l * 128]; s += v[l]; }
#pragma unroll
    for (int o = 16; o > 0; o >>= 1) s += __shfl_xor_sync(0xffffffffu, s, o);
    int warp = tid >> 5, lane = tid & 31;
    if (lane == 0) red[warp] = s;
    __syncthreads();
    float mean = (red[0] + red[1] + red[2] + red[3]) * (1.0f / Cc);
    __syncthreads();
    float sq = 0.f;
#pragma unroll
    for (int l = 0; l < 4; l++) { float d = v[l] - mean; sq += d * d; }
#pragma unroll
    for (int o = 16; o > 0; o >>= 1) sq += __shfl_xor_sync(0xffffffffu, sq, o);
    if (lane == 0) red[warp] = sq;
    __syncthreads();
    float var = (red[0] + red[1] + red[2] + red[3]) * (1.0f / Cc);
    float inv = rsqrtf(var + EPS);

    int t = row / Ss;
#pragma unroll
    for (int l = 0; l < 4; l++) {
        int c = tid + l * 128;
        float val = (v[l] - mean) * inv * gamma[c] + beta[c] + pos[t * Cc + c];
        bf16 h, lo;
        split2(val, h, lo);
        oh[(size_t)row * Cc + c] = h;
        ol[(size_t)row * Cc + c] = lo;
    }
}

// ---------------- fused gate+residual+FFN-LN ----------------
__global__ void gate_ln_kernel(const float* __restrict__ proj,
                               const float* __restrict__ gw, const float* __restrict__ gb,
                               const float* __restrict__ gamma, const float* __restrict__ beta,
                               float* __restrict__ xt, bf16* __restrict__ oh, bf16* __restrict__ ol) {
    __shared__ float red[4];
    int row = blockIdx.x;
    int tid = threadIdx.x;
    int warp = tid >> 5, lane = tid & 31;
    const float* p = proj + (size_t)row * Cc;
    float* xr = xt + (size_t)row * Cc;

    float pv[4], xv[4];
    float s = 0.f;
#pragma unroll
    for (int l = 0; l < 4; l++) {
        int c = tid + l * 128;
        pv[l] = p[c];
        xv[l] = xr[c];
        s += pv[l] * gw[c];
    }
#pragma unroll
    for (int o = 16; o > 0; o >>= 1) s += __shfl_xor_sync(0xffffffffu, s, o);
    if (lane == 0) red[warp] = s;
    __syncthreads();
    float dot = red[0] + red[1] + red[2] + red[3];
    float g = 1.0f / (1.0f + __expf(-(dot + gb[0])));
    __syncthreads();

    float sum = 0.f;
#pragma unroll
    for (int l = 0; l < 4; l++) { xv[l] += pv[l] * g; sum += xv[l]; }
#pragma unroll
    for (int o = 16; o > 0; o >>= 1) sum += __shfl_xor_sync(0xffffffffu, sum, o);
    if (lane == 0) red[warp] = sum;
    __syncthreads();
    float mean = (red[0] + red[1] + red[2] + red[3]) * (1.0f / Cc);
    __syncthreads();
    float sq = 0.f;
#pragma unroll
    for (int l = 0; l < 4; l++) { float d = xv[l] - mean; sq += d * d; }
#pragma unroll
    for (int o = 16; o > 0; o >>= 1) sq += __shfl_xor_sync(0xffffffffu, sq, o);
    if (lane == 0) red[warp] = sq;
    __syncthreads();
    float var = (red[0] + red[1] + red[2] + red[3]) * (1.0f / Cc);
    float inv = rsqrtf(var + EPS);

#pragma unroll
    for (int l = 0; l < 4; l++) {
        int c = tid + l * 128;
        xr[c] = xv[l];
        float val = (xv[l] - mean) * inv * gamma[c] + beta[c];
        bf16 h, lo;
        split2(val, h, lo);
        oh[(size_t)row * Cc + c] = h;
        ol[(size_t)row * Cc + c] = lo;
    }
}

// ---------------- transpose + split body ----------------
__device__ __forceinline__ void tsplit_body(const float* __restrict__ W, bf16* __restrict__ hi,
                                            bf16* __restrict__ lo, int K, int N,
                                            int nb, int kb, int tid) {
    __shared__ float t[64][65];
    int kr = tid >> 4;
    int c4 = tid & 15;
#pragma unroll
    for (int i = 0; i < 4; i++) {
        int k = kr + 16 * i;
        float4 v = *reinterpret_cast<const float4*>(&W[(size_t)(kb + k) * N + nb + c4 * 4]);
        t[c4 * 4 + 0][k] = v.x; t[c4 * 4 + 1][k] = v.y;
        t[c4 * 4 + 2][k] = v.z; t[c4 * 4 + 3][k] = v.w;
    }
    __syncthreads();
    int n = tid >> 2;
    int k0 = (tid & 3) * 16;
    uint32_t hbuf[8], lbuf[8];
#pragma unroll
    for (int j = 0; j < 8; j++) {
        float v0 = t[n][k0 + 2 * j], v1 = t[n][k0 + 2 * j + 1];
        bf16 h0, l0, h1, l1;
        split2(v0, h0, l0); split2(v1, h1, l1);
        __nv_bfloat162 hh; hh.x = h0; hh.y = h1;
        __nv_bfloat162 ll; ll.x = l0; ll.y = l1;
        hbuf[j] = *reinterpret_cast<uint32_t*>(&hh);
        lbuf[j] = *reinterpret_cast<uint32_t*>(&ll);
    }
    size_t o = (size_t)(nb + n) * K + kb + k0;
    *reinterpret_cast<uint4*>(&hi[o])     = *reinterpret_cast<uint4*>(&hbuf[0]);
    *reinterpret_cast<uint4*>(&hi[o + 8]) = *reinterpret_cast<uint4*>(&hbuf[4]);
    *reinterpret_cast<uint4*>(&lo[o])     = *reinterpret_cast<uint4*>(&lbuf[0]);
    *reinterpret_cast<uint4*>(&lo[o + 8]) = *reinterpret_cast<uint4*>(&lbuf[4]);
}

// fused QKV weight split: z=0 wq, z=1 wk (into wqkt at offset), z=2 wv
__global__ void tsplit_qkv(const float* __restrict__ wq, const float* __restrict__ wk,
                           const float* __restrict__ wv,
                           bf16* __restrict__ qkt_h, bf16* __restrict__ qkt_l,
                           bf16* __restrict__ vt_h, bf16* __restrict__ vt_l) {
    int z = blockIdx.z;
    const float* W = (z == 0) ? wq : (z == 1) ? wk : wv;
    bf16* hi = (z == 0) ? qkt_h : (z == 1) ? qkt_h + (size_t)INNER * Cc : vt_h;
    bf16* lo = (z == 0) ? qkt_l : (z == 1) ? qkt_l + (size_t)INNER * Cc : vt_l;
    tsplit_body(W, hi, lo, Cc, INNER, blockIdx.x * 64, blockIdx.y * 64, threadIdx.x);
}

// ---------------- mma.sync bf16 GEMM body (hi/lo split, ldmatrix, 3-stage) -
#define GROW80 80
#define GBUF_A (128 * 80)

template <int BN>
__device__ __forceinline__ void gemm_body(char* smemc,
                                          const bf16* __restrict__ Ah, const bf16* __restrict__ Al,
                                          const bf16* __restrict__ Bh, const bf16* __restrict__ Bl,
                                          const float* __restrict__ bias, const float* __restrict__ resid,
                                          float* __restrict__ outF, bf16* __restrict__ outH,
                                          bf16* __restrict__ outL,
                                          int Nc, int K, int act, int rowBase, int colBase) {
    constexpr int WM = (BN == 128) ? 2 : 4;
    constexpr int MT = (BN == 128) ? 4 : 2;
    constexpr int GBUF_B = BN * 80;
    constexpr int GSTAGE = 2 * GBUF_A + 2 * GBUF_B;

    uint32_t sb = smem_u32(smemc);
    int tid = threadIdx.x, wid = tid >> 5, lane = tid & 31;
    int gr = lane >> 2, cq = lane & 3;
    int mat = lane >> 3, rr = lane & 7;
    int wm = wid % WM, wn = wid / WM;
    int nc = K >> 5;

    const bf16* srcs[4] = { Ah + (size_t)rowBase * K, Al + (size_t)rowBase * K,
                            Bh + (size_t)colBase * K, Bl + (size_t)colBase * K };

    auto load_stage = [&](int kc, int s) {
        uint32_t base = sb + s * GSTAGE;
#pragma unroll
        for (int arr = 0; arr < 4; arr++) {
            int rows = (arr < 2) ? 128 : BN;
            const bf16* src = srcs[arr] + kc * 32;
            uint32_t dstb = base + ((arr < 2) ? arr * GBUF_A : 2 * GBUF_A + (arr - 2) * GBUF_B);
            for (int l = 0; l < rows * 4 / 256; l++) {
                int lin = tid + l * 256;
                int r = lin >> 2, ch = lin & 3;
                cp16(dstb + r * 80 + ch * 16, src + (size_t)r * K + ch * 8);
            }
        }
    };

    load_stage(0, 0); cp_commit();
    load_stage(1, 1); cp_commit();

    float acc[MT][4][4];
#pragma unroll
    for (int a = 0; a < MT; a++)
#pragma unroll
        for (int b = 0; b < 4; b++)
#pragma unroll
            for (int c = 0; c < 4; c++) acc[a][b][c] = 0.f;

    for (int kc = 0; kc < nc; kc++) {
        int s = kc % 3;
        cp_wait1();
        __syncthreads();
        uint32_t A0 = sb + s * GSTAGE, A1 = A0 + GBUF_A;
        uint32_t B0 = A0 + 2 * GBUF_A, B1 = B0 + GBUF_B;
#pragma unroll
        for (int ks = 0; ks < 2; ks++) {
            uint32_t af[2][MT][4];
#pragma unroll
            for (int mt = 0; mt < MT; mt++) {
                uint32_t ra = (uint32_t)(16 * MT * wm + 16 * mt + (mat & 1) * 8 + rr) * GROW80
                            + ks * 32 + (mat >> 1) * 16;
                ldsm4(af[0][mt], A0 + ra);
                ldsm4(af[1][mt], A1 + ra);
            }
#pragma unroll
            for (int ntp = 0; ntp < 2; ntp++) {
                uint32_t rb = (uint32_t)(32 * wn + 16 * ntp + (mat >> 1) * 8 + rr) * GROW80
                            + ks * 32 + (mat & 1) * 16;
                uint32_t bh[4], bl[4];
                ldsm4(bh, B0 + rb);
                ldsm4(bl, B1 + rb);
#pragma unroll
                for (int mt = 0; mt < MT; mt++) {
                    mma16816(acc[mt][2 * ntp], af[0][mt], bh[0], bh[1]);
                    mma16816(acc[mt][2 * ntp], af[0][mt], bl[0], bl[1]);
                    mma16816(acc[mt][2 * ntp], af[1][mt], bh[0], bh[1]);
                    mma16816(acc[mt][2 * ntp + 1], af[0][mt], bh[2], bh[3]);
                    mma16816(acc[mt][2 * ntp + 1], af[0][mt], bl[2], bl[3]);
                    mma16816(acc[mt][2 * ntp + 1], af[1][mt], bh[2], bh[3]);
                }
            }
        }
        if (kc + 2 < nc) load_stage(kc + 2, (kc + 2) % 3);
        cp_commit();
    }

#pragma unroll
    for (int mt = 0; mt < MT; mt++) {
#pragma unroll
        for (int nt = 0; nt < 4; nt++) {
            int col = colBase + 32 * wn + 8 * nt + 2 * cq;
#pragma unroll
            for (int half = 0; half < 2; half++) {
                int row = rowBase + 16 * MT * wm + 16 * mt + gr + 8 * half;
                float v0 = acc[mt][nt][2 * half + 0];
                float v1 = acc[mt][nt][2 * half + 1];
                if (bias) { v0 += bias[col]; v1 += bias[col + 1]; }
                if (resid) {
                    float2 rv = *reinterpret_cast<const float2*>(&resid[(size_t)row * Nc + col]);
                    v0 += rv.x; v1 += rv.y;
                }
                if (act == 1) {
                    v0 = gelu_fast(v0);
                    v1 = gelu_fast(v1);
                }
                if (outF)
                    *reinterpret_cast<float2*>(&outF[(size_t)row * Nc + col]) = make_float2(v0, v1);
                if (outH) {
                    bf16 h0, l0, h1, l1;
                    split2(v0, h0, l0);
                    split2(v1, h1, l1);
                    __nv_bfloat162 hh; hh.x = h0; hh.y = h1;
                    __nv_bfloat162 ll; ll.x = l0; ll.y = l1;
                    *reinterpret_cast<uint32_t*>(&outH[(size_t)row * Nc + col]) =
                        *reinterpret_cast<uint32_t*>(&hh);
                    *reinterpret_cast<uint32_t*>(&outL[(size_t)row * Nc + col]) =
                        *reinterpret_cast<uint32_t*>(&ll);
                }
            }
        }
    }
}

template <int BN>
__global__ void gemm_mma(const bf16* __restrict__ Ah, const bf16* __restrict__ Al,
                         const bf16* __restrict__ Bh, const bf16* __restrict__ Bl,
                         const float* __restrict__ bias, const float* __restrict__ resid,
                         float* __restrict__ outF, bf16* __restrict__ outH, bf16* __restrict__ outL,
                         int Nc, int K, int act) {
    extern __shared__ char smemc[];
    gemm_body<BN>(smemc, Ah, Al, Bh, Bl, bias, resid, outF, outH, outL,
                  Nc, K, act, blockIdx.y * 128, blockIdx.x * BN);
}

// combined QKV projection: grid (24, 18); x<16 -> QK gemm, x>=16 -> V gemm
__global__ void gemm_qkv(const bf16* __restrict__ xnh, const bf16* __restrict__ xnl,
                         const bf16* __restrict__ ynh, const bf16* __restrict__ ynl,
                         const bf16* __restrict__ wqkth, const bf16* __restrict__ wqktl,
                         const bf16* __restrict__ wvth, const bf16* __restrict__ wvtl,
                         float* __restrict__ qk, float* __restrict__ v) {
    extern __shared__ char smemc[];
    int cx = blockIdx.x;
    if (cx < 16) {
        gemm_body<128>(smemc, xnh, xnl, wqkth, wqktl, nullptr, nullptr,
                       qk, nullptr, nullptr, QKN, Cc, 0, blockIdx.y * 128, cx * 128);
    } else {
        gemm_body<128>(smemc, ynh, ynl, wvth, wvtl, nullptr, nullptr,
                       v, nullptr, nullptr, INNER, Cc, 0, blockIdx.y * 128, (cx - 16) * 128);
    }
}

#define GEMM_SMEM128 (3 * (2 * GBUF_A + 2 * 128 * 80))  // 122880
#define GEMM_SMEM64  (3 * (2 * GBUF_A + 2 * 64 * 80))   // 92160

// ---------------- rope table ----------------
__global__ void rope_tab(float* __restrict__ rc, float* __restrict__ rs) {
    int idx = blockIdx.x * blockDim.x + threadIdx.x;
    if (idx >= Nn_TOK * 32) return;
    int j = idx & 31, n = idx >> 5;
    const float LOG1E4_OVER32 = 9.210340371976184f / 32.0f;
    float f = __expf(-(float)j * LOG1E4_OVER32);
    float ang = (float)n * f;
    rc[idx] = cosf(ang);
    rs[idx] = sinf(ang);
}

// ---------------- RoPE body (hi-only q,k), 256 threads/block ----------
__device__ __forceinline__ void rope_body(int idx, const float* __restrict__ qk,
                                          const float* __restrict__ rc, const float* __restrict__ rs,
                                          bf16* __restrict__ qh_, bf16* __restrict__ kh_) {
    int j8 = idx & 3;
    int nh = idx >> 2;
    int h = nh & 15;
    int n = nh >> 4;
    int j = j8 * 8;

    float c[8], s[8], a[8], b[8], ka[8], kb[8];
    *reinterpret_cast<float4*>(c)     = *reinterpret_cast<const float4*>(&rc[n * 32 + j]);
    *reinterpret_cast<float4*>(c + 4) = *reinterpret_cast<const float4*>(&rc[n * 32 + j + 4]);
    *reinterpret_cast<float4*>(s)     = *reinterpret_cast<const float4*>(&rs[n * 32 + j]);
    *reinterpret_cast<float4*>(s + 4) = *reinterpret_cast<const float4*>(&rs[n * 32 + j + 4]);

    size_t srcq = (size_t)n * QKN + h * DH;
    size_t srck = srcq + INNER;
    *reinterpret_cast<float4*>(a)      = *reinterpret_cast<const float4*>(&qk[srcq + j]);
    *reinterpret_cast<float4*>(a + 4)  = *reinterpret_cast<const float4*>(&qk[srcq + j + 4]);
    *reinterpret_cast<float4*>(b)      = *reinterpret_cast<const float4*>(&qk[srcq + j + 32]);
    *reinterpret_cast<float4*>(b + 4)  = *reinterpret_cast<const float4*>(&qk[srcq + j + 36]);
    *reinterpret_cast<float4*>(ka)     = *reinterpret_cast<const float4*>(&qk[srck + j]);
    *reinterpret_cast<float4*>(ka + 4) = *reinterpret_cast<const float4*>(&qk[srck + j + 4]);
    *reinterpret_cast<float4*>(kb)     = *reinterpret_cast<const float4*>(&qk[srck + j + 32]);
    *reinterpret_cast<float4*>(kb + 4) = *reinterpret_cast<const float4*>(&qk[srck + j + 36]);

    size_t dst = ((size_t)h * Nn_TOK + n) * DH;
    uint32_t qh1[4], qh2[4], kh1[4], kh2[4];
#pragma unroll
    for (int i = 0; i < 4; i++) {
        float r1a = a[2 * i] * c[2 * i] - b[2 * i] * s[2 * i];
        float r1b = a[2 * i + 1] * c[2 * i + 1] - b[2 * i + 1] * s[2 * i + 1];
        float r2a = b[2 * i] * c[2 * i] + a[2 * i] * s[2 * i];
        float r2b = b[2 * i + 1] * c[2 * i + 1] + a[2 * i + 1] * s[2 * i + 1];
        qh1[i] = packbf(r1a, r1b);
        qh2[i] = packbf(r2a, r2b);

        float k1a = ka[2 * i] * c[2 * i] - kb[2 * i] * s[2 * i];
        float k1b = ka[2 * i + 1] * c[2 * i + 1] - kb[2 * i + 1] * s[2 * i + 1];
        float k2a = kb[2 * i] * c[2 * i] + ka[2 * i] * s[2 * i];
        float k2b = kb[2 * i + 1] * c[2 * i + 1] + ka[2 * i + 1] * s[2 * i + 1];
        kh1[i] = packbf(k1a, k1b);
        kh2[i] = packbf(k2a, k2b);
    }
    *reinterpret_cast<uint4*>(&qh_[dst + j])      = *reinterpret_cast<uint4*>(qh1);
    *reinterpret_cast<uint4*>(&qh_[dst + j + 32]) = *reinterpret_cast<uint4*>(qh2);
    *reinterpret_cast<uint4*>(&kh_[dst + j])      = *reinterpret_cast<uint4*>(kh1);
    *reinterpret_cast<uint4*>(&kh_[dst + j + 32]) = *reinterpret_cast<uint4*>(kh2);
}

// ---------------- V transpose + split body (64x64 tile) ----------
__device__ __forceinline__ void vt_body(int n0, int h, const float* __restrict__ v,
                                        bf16* __restrict__ vh_, bf16* __restrict__ vl_) {
    __shared__ float tsm[64][65];
    int tid = threadIdx.x;
    int r = tid >> 4, c4 = tid & 15;
#pragma unroll
    for (int i = 0; i < 4; i++) {
        int row = r + 16 * i;
        float4 val = *reinterpret_cast<const float4*>(&v[(size_t)(n0 + row) * INNER + h * DH + c4 * 4]);
        tsm[c4 * 4 + 0][row] = val.x; tsm[c4 * 4 + 1][row] = val.y;
        tsm[c4 * 4 + 2][row] = val.z; tsm[c4 * 4 + 3][row] = val.w;
    }
    __syncthreads();
    int d = tid >> 2;
    int nn0 = (tid & 3) * 16;
    uint32_t hbuf[8], lbuf[8];
#pragma unroll
    for (int j = 0; j < 8; j++) {
        float v0 = tsm[d][nn0 + 2 * j], v1 = tsm[d][nn0 + 2 * j + 1];
        bf16 h0, l0, h1, l1;
        split2(v0, h0, l0); split2(v1, h1, l1);
        __nv_bfloat162 hh; hh.x = h0; hh.y = h1;
        __nv_bfloat162 ll; ll.x = l0; ll.y = l1;
        hbuf[j] = *reinterpret_cast<uint32_t*>(&hh);
        lbuf[j] = *reinterpret_cast<uint32_t*>(&ll);
    }
    size_t o = ((size_t)h * DH + d) * Nn_TOK + n0 + nn0;
    *reinterpret_cast<uint4*>(&vh_[o])     = *reinterpret_cast<uint4*>(&hbuf[0]);
    *reinterpret_cast<uint4*>(&vh_[o + 8]) = *reinterpret_cast<uint4*>(&hbuf[4]);
    *reinterpret_cast<uint4*>(&vl_[o])     = *reinterpret_cast<uint4*>(&lbuf[0]);
    *reinterpret_cast<uint4*>(&vl_[o + 8]) = *reinterpret_cast<uint4*>(&lbuf[4]);
}

// ---------------- combined prep: vt_split (576) | rope (576) | tsplit3 (640)
// grid 1792 x 256 threads
__global__ void prep_all(const float* __restrict__ v, bf16* __restrict__ vh_, bf16* __restrict__ vl_,
                         const float* __restrict__ qk,
                         const float* __restrict__ rc, const float* __restrict__ rs,
                         bf16* __restrict__ qh_, bf16* __restrict__ kh_,
                         const float* __restrict__ ow, const float* __restrict__ w1,
                         const float* __restrict__ w2,
                         bf16* __restrict__ owh, bf16* __restrict__ owl,
                         bf16* __restrict__ w1h, bf16* __restrict__ w1l,
                         bf16* __restrict__ w2h, bf16* __restrict__ w2l) {
    int b = blockIdx.x;
    if (b < 576) {
        // vt_split: 36 n-tiles x 16 heads
        vt_body((b % 36) * 64, b / 36, v, vh_, vl_);
    } else if (b < 1152) {
        // rope: indices cover Nn_TOK*HEADS*4 = 147456 = 576*256 exactly
        rope_body((b - 576) * 256 + threadIdx.x, qk, rc, rs, qh_, kh_);
    } else {
        int lb = b - 1152;
        const float* W; bf16 *hi, *lo; int K, N;
        if (lb < 128)      { W = ow; hi = owh; lo = owl; K = INNER; N = Cc; }
        else if (lb < 384) { W = w1; hi = w1h; lo = w1l; K = Cc;    N = MLP; lb -= 128; }
        else               { W = w2; hi = w2h; lo = w2l; K = MLP;   N = Cc;  lb -= 384; }
        int nT = N / 64;
        tsplit_body(W, hi, lo, K, N, (lb % nT) * 64, (lb / nT) * 64, threadIdx.x);
    }
}

// ---------------- flash attention via mma.sync + ldmatrix (3-stage) -------
// 128 q-rows / CTA, 256 threads. Q hi-only, K hi-only; V hi+lo. log2-domain softmax.
#define AST144 144
#define ATILE (64 * 144)
#define ASTAGE (3 * ATILE)       // Kh, Vh, Vl
#define ATTN_SMEM (3 * ASTAGE)   // 82944 B

__global__ __launch_bounds__(256)
void attn_mma(const bf16* __restrict__ qh, const bf16* __restrict__ kh,
              const bf16* __restrict__ vth, const bf16* __restrict__ vtl,
              const int* __restrict__ mask,
              bf16* __restrict__ oh, bf16* __restrict__ ol) {
    extern __shared__ char smemc[];
    uint32_t sb = smem_u32(smemc);
    int h = blockIdx.y;
    int qbase = blockIdx.x * 128;
    int tid = threadIdx.x, w = tid >> 5, lane = tid & 31;
    int gr = lane >> 2, cq = lane & 3;
    int mat = lane >> 3, rr = lane & 7;

    const bf16* qh_p = qh + ((size_t)h * Nn_TOK + qbase) * DH;
    const bf16* kh_p = kh + (size_t)h * Nn_TOK * DH;
    const bf16* vh_p = vth + (size_t)h * DH * Nn_TOK;
    const bf16* vl_p = vtl + (size_t)h * DH * Nn_TOK;

    // ---- stage Q (hi only), extract fragments ----
    {
        int r = tid >> 1, half = tid & 1;
        const uint4* s0 = reinterpret_cast<const uint4*>(qh_p + r * DH + half * 32);
        uint4* d0 = reinterpret_cast<uint4*>(smemc + r * 144 + half * 64);
#pragma unroll
        for (int c = 0; c < 4; c++) d0[c] = s0[c];
    }
    __syncthreads();
    uint32_t qfh[4][4];
#pragma unroll
    for (int ks = 0; ks < 4; ks++) {
        uint32_t ra = (uint32_t)(16 * w + (mat & 1) * 8 + rr) * AST144 + ks * 32 + (mat >> 1) * 16;
        ldsm4(qfh[ks], sb + ra);
    }
    __syncthreads();

    auto load_tile = [&](int kt, int s) {
        int k0 = kt * 64;
        uint32_t base = sb + s * ASTAGE;
#pragma unroll
        for (int l = 0; l < 2; l++) {
            int lin = tid + l * 256;
            int r = lin >> 3, ch = lin & 7;
            cp16(base + r * 144 + ch * 16, kh_p + (size_t)(k0 + r) * DH + ch * 8);
            cp16(base + ATILE + r * 144 + ch * 16, vh_p + (size_t)r * Nn_TOK + k0 + ch * 8);
            cp16(base + 2 * ATILE + r * 144 + ch * 16, vl_p + (size_t)r * Nn_TOK + k0 + ch * 8);
        }
    };

    load_tile(0, 0); cp_commit();
    load_tile(1, 1); cp_commit();

    float O[8][4];
#pragma unroll
    for (int a = 0; a < 8; a++)
#pragma unroll
        for (int b = 0; b < 4; b++) O[a][b] = 0.f;
    float m0 = -1e30f, m1 = -1e30f, l0 = 0.f, l1 = 0.f;

    int row0 = qbase + 16 * w + gr;
    int row1 = row0 + 8;
    int tq0 = row0 / Ss, tq1 = row1 / Ss;

    const int NT = Nn_TOK / 64;
    for (int kt = 0; kt < NT; kt++) {
        int s = kt % 3;
        cp_wait1();
        __syncthreads();
        uint32_t K0 = sb + s * ASTAGE;
        uint32_t V0 = K0 + ATILE, V1 = K0 + 2 * ATILE;

        float S[8][4];
#pragma unroll
        for (int a = 0; a < 8; a++)
#pragma unroll
            for (int b = 0; b < 4; b++) S[a][b] = 0.f;
#pragma unroll
        for (int ks = 0; ks < 4; ks++) {
#pragma unroll
            for (int ntp = 0; ntp < 4; ntp++) {
                uint32_t rb = (uint32_t)(16 * ntp + (mat >> 1) * 8 + rr) * AST144
                            + ks * 32 + (mat & 1) * 16;
                uint32_t bh[4];
                ldsm4(bh, K0 + rb);
                mma16816(S[2 * ntp], qfh[ks], bh[0], bh[1]);
                mma16816(S[2 * ntp + 1], qfh[ks], bh[2], bh[3]);
            }
        }

        // ---- mask + online softmax (log2 domain) ----
        int k0 = kt * 64;
        int tk0c = k0 / Ss;
        int change = (tk0c + 1) * Ss - k0;
        int m00 = mask[tq0 * Tt + tk0c];
        int m10 = mask[tq1 * Tt + tk0c];
        int m01 = (change < 64) ? mask[tq0 * Tt + tk0c + 1] : 1;
        int m11 = (change < 64) ? mask[tq1 * Tt + tk0c + 1] : 1;
        float b00 = m00 ? 0.f : -1e30f, b01 = m01 ? 0.f : -1e30f;
        float b10 = m10 ? 0.f : -1e30f, b11 = m11 ? 0.f : -1e30f;

        float mx0 = -1e30f, mx1 = -1e30f;
#pragma unroll
        for (int nt = 0; nt < 8; nt++) {
            int colb = 8 * nt + 2 * cq;
            float bi0 = (colb >= change) ? b01 : b00;
            float bi1 = (colb >= change) ? b11 : b10;
            S[nt][0] = S[nt][0] * SC2 + bi0;
            S[nt][1] = S[nt][1] * SC2 + bi0;
            S[nt][2] = S[nt][2] * SC2 + bi1;
            S[nt][3] = S[nt][3] * SC2 + bi1;
            mx0 = fmaxf(mx0, fmaxf(S[nt][0], S[nt][1]));
            mx1 = fmaxf(mx1, fmaxf(S[nt][2], S[nt][3]));
        }
        mx0 = fmaxf(mx0, __shfl_xor_sync(0xffffffffu, mx0, 1));
        mx0 = fmaxf(mx0, __shfl_xor_sync(0xffffffffu, mx0, 2));
        mx1 = fmaxf(mx1, __shfl_xor_sync(0xffffffffu, mx1, 1));
        mx1 = fmaxf(mx1, __shfl_xor_sync(0xffffffffu, mx1, 2));
        float mn0 = fmaxf(m0, mx0), mn1 = fmaxf(m1, mx1);
        float al0 = exp2f(m0 - mn0), al1 = exp2f(m1 - mn1);

        float rs0 = 0.f, rs1 = 0.f;
#pragma unroll
        for (int nt = 0; nt < 8; nt++) {
            S[nt][0] = exp2f(S[nt][0] - mn0);
            S[nt][1] = exp2f(S[nt][1] - mn0);
            S[nt][2] = exp2f(S[nt][2] - mn1);
            S[nt][3] = exp2f(S[nt][3] - mn1);
            rs0 += S[nt][0] + S[nt][1];
            rs1 += S[nt][2] + S[nt][3];
        }
        rs0 += __shfl_xor_sync(0xffffffffu, rs0, 1);
        rs0 += __shfl_xor_sync(0xffffffffu, rs0, 2);
        rs1 += __shfl_xor_sync(0xffffffffu, rs1, 1);
        rs1 += __shfl_xor_sync(0xffffffffu, rs1, 2);
        l0 = l0 * al0 + rs0;
        l1 = l1 * al1 + rs1;
        m0 = mn0; m1 = mn1;
#pragma unroll
        for (int nt = 0; nt < 8; nt++) {
            O[nt][0] *= al0; O[nt][1] *= al0;
            O[nt][2] *= al1; O[nt][3] *= al1;
        }

        uint32_t pa[4][4];
#pragma unroll
        for (int t = 0; t < 4; t++) {
            pa[t][0] = packbf(S[2 * t][0], S[2 * t][1]);
            pa[t][1] = packbf(S[2 * t][2], S[2 * t][3]);
            pa[t][2] = packbf(S[2 * t + 1][0], S[2 * t + 1][1]);
            pa[t][3] = packbf(S[2 * t + 1][2], S[2 * t + 1][3]);
        }

#pragma unroll
        for (int t = 0; t < 4; t++) {
#pragma unroll
            for (int ntp = 0; ntp < 4; ntp++) {
                uint32_t rv = (uint32_t)(16 * ntp + (mat >> 1) * 8 + rr) * AST144
                            + t * 32 + (mat & 1) * 16;
                uint32_t vh[4], vl[4];
                ldsm4(vh, V0 + rv);
                ldsm4(vl, V1 + rv);
                mma16816(O[2 * ntp], pa[t], vh[0], vh[1]);
                mma16816(O[2 * ntp], pa[t], vl[0], vl[1]);
                mma16816(O[2 * ntp + 1], pa[t], vh[2], vh[3]);
                mma16816(O[2 * ntp + 1], pa[t], vl[2], vl[3]);
            }
        }
        if (kt + 2 < NT) load_tile(kt + 2, (kt + 2) % 3);
        cp_commit();
    }

    float inv0 = 1.0f / l0, inv1 = 1.0f / l1;
#pragma unroll
    for (int nt = 0; nt < 8; nt++) {
        int col = h * DH + 8 * nt + 2 * cq;
        float v0 = O[nt][0] * inv0, v1 = O[nt][1] * inv0;
        float v2 = O[nt][2] * inv1, v3 = O[nt][3] * inv1;
        bf16 h0, lo0, h1, lo1;
        split2(v0, h0, lo0); split2(v1, h1, lo1);
        __nv_bfloat162 hh; hh.x = h0; hh.y = h1;
        __nv_bfloat162 ll; ll.x = lo0; ll.y = lo1;
        *reinterpret_cast<uint32_t*>(&oh[(size_t)row0 * INNER + col]) = *reinterpret_cast<uint32_t*>(&hh);
        *reinterpret_cast<uint32_t*>(&ol[(size_t)row0 * INNER + col]) = *reinterpret_cast<uint32_t*>(&ll);
        split2(v2, h0, lo0); split2(v3, h1, lo1);
        hh.x = h0; hh.y = h1; ll.x = lo0; ll.y = lo1;
        *reinterpret_cast<uint32_t*>(&oh[(size_t)row1 * INNER + col]) = *reinterpret_cast<uint32_t*>(&hh);
        *reinterpret_cast<uint32_t*>(&ol[(size_t)row1 * INNER + col]) = *reinterpret_cast<uint32_t*>(&ll);
    }
}

// ---------------- host orchestration ----------------
extern "C" void kernel_launch(void* const* d_in, const int* in_sizes, int n_in,
                              void* d_out, int out_size) {
    const float* x        = (const float*)d_in[0];
    const float* y        = (const float*)d_in[1];
    const int*   mask     = (const int*)  d_in[2];
    const float* normx_g  = (const float*)d_in[3];
    const float* normx_b  = (const float*)d_in[4];
    const float* normy_g  = (const float*)d_in[5];
    const float* normy_b  = (const float*)d_in[6];
    const float* wq       = (const float*)d_in[7];
    const float* wk       = (const float*)d_in[8];
    const float* wv       = (const float*)d_in[9];
    const float* temp_pos = (const float*)d_in[10];
    const float* gate_w   = (const float*)d_in[11];
    const float* gate_b   = (const float*)d_in[12];
    const float* out_w    = (const float*)d_in[13];
    const float* out_b    = (const float*)d_in[14];
    const float* ffn_g    = (const float*)d_in[15];
    const float* ffn_b    = (const float*)d_in[16];
    const float* w1       = (const float*)d_in[17];
    const float* b1       = (const float*)d_in[18];
    const float* w2       = (const float*)d_in[19];
    const float* b2       = (const float*)d_in[20];
    float* out = (float*)d_out;

#define SYM(v, s) cudaGetSymbolAddress((void**)&v, s)
    float *p_xt, *p_yt, *p_proj, *p_qk, *p_v, *p_rc, *p_rs;
    bf16 *p_xn_h, *p_xn_l, *p_yn_h, *p_yn_l, *p_ao_h, *p_ao_l, *p_h_h, *p_h_l;
    bf16 *p_qh, *p_kh, *p_vth, *p_vtl;
    bf16 *p_wqkt_h, *p_wqkt_l, *p_wvt_h, *p_wvt_l;
    bf16 *p_owt_h, *p_owt_l, *p_w1t_h, *p_w1t_l, *p_w2t_h, *p_w2t_l;
    SYM(p_xt, g_xt); SYM(p_yt, g_yt); SYM(p_proj, g_proj);
    SYM(p_qk, g_qk); SYM(p_v, g_v); SYM(p_rc, g_rcos); SYM(p_rs, g_rsin);
    SYM(p_xn_h, g_xn_h); SYM(p_xn_l, g_xn_l); SYM(p_yn_h, g_yn_h); SYM(p_yn_l, g_yn_l);
    SYM(p_ao_h, g_ao_h); SYM(p_ao_l, g_ao_l); SYM(p_h_h, g_h_h); SYM(p_h_l, g_h_l);
    SYM(p_qh, g_qh); SYM(p_kh, g_kh);
    SYM(p_vth, g_vth); SYM(p_vtl, g_vtl);
    SYM(p_wqkt_h, g_wqkt_h); SYM(p_wqkt_l, g_wqkt_l);
    SYM(p_wvt_h, g_wvt_h); SYM(p_wvt_l, g_wvt_l);
    SYM(p_owt_h, g_owt_h); SYM(p_owt_l, g_owt_l);
    SYM(p_w1t_h, g_w1t_h); SYM(p_w1t_l, g_w1t_l);
    SYM(p_w2t_h, g_w2t_h); SYM(p_w2t_l, g_w2t_l);
#undef SYM

    static bool attr_set = false;
    if (!attr_set) {
        cudaFuncSetAttribute(gemm_mma<128>, cudaFuncAttributeMaxDynamicSharedMemorySize, GEMM_SMEM128);
        cudaFuncSetAttribute(gemm_mma<64>, cudaFuncAttributeMaxDynamicSharedMemorySize, GEMM_SMEM64);
        cudaFuncSetAttribute(gemm_qkv, cudaFuncAttributeMaxDynamicSharedMemorySize, GEMM_SMEM128);
        cudaFuncSetAttribute(attn_mma, cudaFuncAttributeMaxDynamicSharedMemorySize, ATTN_SMEM);
        attr_set = true;
    }

    pack_in_kernel<<<dim3(Ss / 16, Cc / 64, Tt), 256>>>(x, y, p_xt, p_yt);
    rope_tab<<<(Nn_TOK * 32 + 255) / 256, 256>>>(p_rc, p_rs);

    for (int i = 0; i < DEPTH; i++) {
        const float* wq_i = wq + (size_t)i * Cc * INNER;
        const float* wk_i = wk + (size_t)i * Cc * INNER;
        const float* wv_i = wv + (size_t)i * Cc * INNER;
        const float* tp_i = temp_pos + (size_t)i * MAXT * Cc;
        const float* ow_i = out_w + (size_t)i * INNER * Cc;
        const float* ob_i = out_b + (size_t)i * Cc;
        const float* gw_i = gate_w + (size_t)i * Cc;
        const float* gb_i = gate_b + i;
        const float* w1_i = w1 + (size_t)i * Cc * MLP;
        const float* b1_i = b1 + (size_t)i * MLP;
        const float* w2_i = w2 + (size_t)i * MLP * Cc;
        const float* b2_i = b2 + (size_t)i * Cc;

        ln2_kernel<<<dim3(Nn_TOK, 2), 128>>>(p_xt, p_yt, p_xn_h, p_xn_l, p_yn_h, p_yn_l,
                                             normx_g + i * Cc, normx_b + i * Cc,
                                             normy_g + i * Cc, normy_b + i * Cc, tp_i);
        tsplit_qkv<<<dim3(INNER / 64, Cc / 64, 3), 256>>>(wq_i, wk_i, wv_i,
                                                          p_wqkt_h, p_wqkt_l, p_wvt_h, p_wvt_l);

        // combined QK + V projection (432 CTAs)
        gemm_qkv<<<dim3(24, Nn_TOK / 128), 256, GEMM_SMEM128>>>(
            p_xn_h, p_xn_l, p_yn_h, p_yn_l,
            p_wqkt_h, p_wqkt_l, p_wvt_h, p_wvt_l, p_qk, p_v);

        // combined vt_split | rope | ow/w1/w2 splits (1792 CTAs)
        prep_all<<<1792, 256>>>(p_v, p_vth, p_vtl, p_qk, p_rc, p_rs, p_qh, p_kh,
                                ow_i, w1_i, w2_i,
                                p_owt_h, p_owt_l, p_w1t_h, p_w1t_l, p_w2t_h, p_w2t_l);

        dim3 ga(Nn_TOK / 128, HEADS);
        attn_mma<<<ga, 256, ATTN_SMEM>>>(p_qh, p_kh, p_vth, p_vtl, mask, p_ao_h, p_ao_l);

        dim3 gp(Cc / 64, Nn_TOK / 128);
        gemm_mma<64><<<gp, 256, GEMM_SMEM64>>>(p_ao_h, p_ao_l, p_owt_h, p_owt_l,
                                               ob_i, nullptr, p_proj, nullptr, nullptr, Cc, INNER, 0);

        gate_ln_kernel<<<Nn_TOK, 128>>>(p_proj, gw_i, gb_i, ffn_g + i * Cc, ffn_b + i * Cc,
                                        p_xt, p_xn_h, p_xn_l);

        dim3 g1(MLP / 128, Nn_TOK / 128);
        gemm_mma<128><<<g1, 256, GEMM_SMEM128>>>(p_xn_h, p_xn_l, p_w1t_h, p_w1t_l,
                                                 b1_i, nullptr, nullptr, p_h_h, p_h_l, MLP, Cc, 1);
        dim3 g2(Cc / 64, Nn_TOK / 128);
        gemm_mma<64><<<g2, 256, GEMM_SMEM64>>>(p_h_h, p_h_l, p_w2t_h, p_w2t_l,
                                               b2_i, p_xt, p_xt, nullptr, nullptr, Cc, MLP, 0);
    }

    pack_out_kernel<<<dim3(Ss / 16, Cc / 64, Tt), 256>>>(p_xt, out);
}